// round 4
// baseline (speedup 1.0000x reference)
#include <cuda_runtime.h>
#include <math.h>

#define Bx 4
#define Lx 2048
#define Dx 512
#define Hx 8
#define DHx 64
#define BHx 32
#define KTOP 38
#define KHALF 19
#define SCALEF 0.125f
#define QSTRIDE 66   // == 2 mod 32 -> conflict-free b[j] LDS, float2-aligned

// ---------------- scratch (device globals; no allocation allowed) ----------
__device__ float g_Q[BHx * Lx * DHx];      // 16 MB, [bh][l][d]
__device__ float g_K[BHx * Lx * DHx];      // 16 MB
__device__ float g_V[BHx * Lx * DHx];      // 16 MB
__device__ float g_M[BHx * Lx];            // sparsity measure per (bh, q)
__device__ int   g_top[BHx * KTOP];
__device__ float g_Ksum[BHx * DHx];        // raw column sum of K
__device__ float g_Vsum[BHx * DHx];        // raw column sum of V
__device__ float g_Vmean[BHx * DHx];
__device__ float g_delta[BHx * KTOP * DHx];  // ctx_sparse - Vmean
__device__ float g_base[Bx * Dx];            // (cat Vmean) @ Wo + bo per batch

// ---------------------------------------------------------------------------
// Projection GEMM: Y = X[8192,512] @ W[512,512] + b, output in [bh][l][d] layout.
// ---------------------------------------------------------------------------
__global__ __launch_bounds__(256)
void proj_kernel(const float* __restrict__ X, const float* __restrict__ W,
                 const float* __restrict__ bias, float* __restrict__ out)
{
    __shared__ float As[16][132];  // [k][m], padded
    __shared__ float Bs[16][128];  // [k][n]

    const int tid = threadIdx.x;
    const int tx = tid & 15;
    const int ty = tid >> 4;
    const int mbase = blockIdx.y * 128;
    const int nbase = blockIdx.x * 128;

    float acc[8][8];
#pragma unroll
    for (int i = 0; i < 8; i++)
#pragma unroll
        for (int j = 0; j < 8; j++) acc[i][j] = 0.f;

    for (int kt = 0; kt < Dx; kt += 16) {
#pragma unroll
        for (int it = 0; it < 2; it++) {
            int lin = tid + it * 256;          // 0..511
            int m = lin >> 2;                  // 0..127
            int c4 = lin & 3;                  // 0..3
            float4 v = *reinterpret_cast<const float4*>(
                X + (size_t)(mbase + m) * Dx + kt + c4 * 4);
            As[c4 * 4 + 0][m] = v.x;
            As[c4 * 4 + 1][m] = v.y;
            As[c4 * 4 + 2][m] = v.z;
            As[c4 * 4 + 3][m] = v.w;
        }
#pragma unroll
        for (int it = 0; it < 2; it++) {
            int lin = tid + it * 256;
            int n4 = lin & 31;
            int k = lin >> 5;
            float4 v = *reinterpret_cast<const float4*>(
                W + (size_t)(kt + k) * Dx + nbase + n4 * 4);
            *reinterpret_cast<float4*>(&Bs[k][n4 * 4]) = v;
        }
        __syncthreads();
#pragma unroll
        for (int kk = 0; kk < 16; kk++) {
            float a[8], b[8];
#pragma unroll
            for (int i = 0; i < 8; i++) a[i] = As[kk][ty + 16 * i];
#pragma unroll
            for (int j = 0; j < 8; j++) b[j] = Bs[kk][tx + 16 * j];
#pragma unroll
            for (int i = 0; i < 8; i++)
#pragma unroll
                for (int j = 0; j < 8; j++) acc[i][j] += a[i] * b[j];
        }
        __syncthreads();
    }

#pragma unroll
    for (int i = 0; i < 8; i++) {
        int r = mbase + ty + 16 * i;
        int b = r >> 11;
        int l = r & 2047;
#pragma unroll
        for (int j = 0; j < 8; j++) {
            int c = nbase + tx + 16 * j;
            int h = c >> 6;
            int d = c & 63;
            out[(((size_t)(b * Hx + h)) * Lx + l) * DHx + d] = acc[i][j] + bias[c];
        }
    }
}

// ---------------------------------------------------------------------------
// Parallel K column-sum / V column-sum: grid (BHx, 16), 128 rows per block.
// ---------------------------------------------------------------------------
__global__ void zero_sums_kernel()
{
    int i = blockIdx.x * blockDim.x + threadIdx.x;
    if (i < BHx * DHx) { g_Ksum[i] = 0.f; g_Vsum[i] = 0.f; }
}

__global__ void partial_sums_kernel()
{
    const int bh = blockIdx.x;
    const int kb = blockIdx.y * 128;
    const int tid = threadIdx.x;
    const int d = tid & 63, s = tid >> 6;  // 4 slices of 32 rows
    float ks = 0.f, vs = 0.f;
    for (int k = kb + s; k < kb + 128; k += 4) {
        ks += g_K[((size_t)bh * Lx + k) * DHx + d];
        vs += g_V[((size_t)bh * Lx + k) * DHx + d];
    }
    __shared__ float red[2][256];
    red[0][tid] = ks;
    red[1][tid] = vs;
    __syncthreads();
    if (tid < 64) {
        float a = red[0][d] + red[0][d + 64] + red[0][d + 128] + red[0][d + 192];
        float b = red[1][d] + red[1][d + 64] + red[1][d + 128] + red[1][d + 192];
        atomicAdd(&g_Ksum[bh * DHx + d], a);
        atomicAdd(&g_Vsum[bh * DHx + d], b);
    }
}

__global__ void finalize_vmean_kernel()
{
    int i = blockIdx.x * blockDim.x + threadIdx.x;
    if (i < BHx * DHx) g_Vmean[i] = g_Vsum[i] * (1.0f / Lx);
}

// ---------------------------------------------------------------------------
// Row stats: M[bh][q] = SCALE * ( max_k Q·K[k]  -  Q·Ksum / L )
// Tiles [row][d] with stride 66 -> conflict-free LDS on the b[j] stream.
// Dynamic smem: 2 * 128 * 66 * 4 = 67584 bytes.
// ---------------------------------------------------------------------------
__global__ __launch_bounds__(256)
void score_kernel()
{
    extern __shared__ float sm[];
    float* Qs = sm;                    // 128 rows, stride QSTRIDE
    float* Ks = sm + 128 * QSTRIDE;

    const int bh = blockIdx.y;
    const int qbase = blockIdx.x * 128;
    const int tid = threadIdx.x;
    const int tx = tid & 15;
    const int ty = tid >> 4;

    const float* Qg = g_Q + ((size_t)bh * Lx + qbase) * DHx;
#pragma unroll
    for (int it = 0; it < 8; it++) {
        int lin = tid + it * 256;
        int c4 = lin & 15, r = lin >> 4;
        float4 v = *reinterpret_cast<const float4*>(Qg + r * 64 + c4 * 4);
        float* p = Qs + r * QSTRIDE + c4 * 4;
        *reinterpret_cast<float2*>(p)     = make_float2(v.x, v.y);
        *reinterpret_cast<float2*>(p + 2) = make_float2(v.z, v.w);
    }

    float rmax[8];
#pragma unroll
    for (int i = 0; i < 8; i++) rmax[i] = -1e30f;

    for (int kb = 0; kb < Lx; kb += 128) {
        __syncthreads();
        const float* Kg = g_K + ((size_t)bh * Lx + kb) * DHx;
#pragma unroll
        for (int it = 0; it < 8; it++) {
            int lin = tid + it * 256;
            int c4 = lin & 15, r = lin >> 4;
            float4 v = *reinterpret_cast<const float4*>(Kg + r * 64 + c4 * 4);
            float* p = Ks + r * QSTRIDE + c4 * 4;
            *reinterpret_cast<float2*>(p)     = make_float2(v.x, v.y);
            *reinterpret_cast<float2*>(p + 2) = make_float2(v.z, v.w);
        }
        __syncthreads();

        float acc[8][8];
#pragma unroll
        for (int i = 0; i < 8; i++)
#pragma unroll
            for (int j = 0; j < 8; j++) acc[i][j] = 0.f;

#pragma unroll 8
        for (int d = 0; d < 64; d++) {
            float a[8], b[8];
#pragma unroll
            for (int i = 0; i < 8; i++) a[i] = Qs[(ty + 16 * i) * QSTRIDE + d];
#pragma unroll
            for (int j = 0; j < 8; j++) b[j] = Ks[(tx + 16 * j) * QSTRIDE + d];
#pragma unroll
            for (int i = 0; i < 8; i++)
#pragma unroll
                for (int j = 0; j < 8; j++) acc[i][j] += a[i] * b[j];
        }
#pragma unroll
        for (int i = 0; i < 8; i++) {
            float m = acc[i][0];
#pragma unroll
            for (int j = 1; j < 8; j++) m = fmaxf(m, acc[i][j]);
            rmax[i] = fmaxf(rmax[i], m);
        }
    }

#pragma unroll
    for (int i = 0; i < 8; i++) {
        float m = rmax[i];
        m = fmaxf(m, __shfl_xor_sync(0xffffffffu, m, 1));
        m = fmaxf(m, __shfl_xor_sync(0xffffffffu, m, 2));
        m = fmaxf(m, __shfl_xor_sync(0xffffffffu, m, 4));
        m = fmaxf(m, __shfl_xor_sync(0xffffffffu, m, 8));
        rmax[i] = m;
    }

    if (tx == 0) {
        const float* ks = g_Ksum + bh * DHx;
#pragma unroll
        for (int i = 0; i < 8; i++) {
            int q = ty + 16 * i;
            float dot = 0.f;
#pragma unroll 16
            for (int d = 0; d < 64; d++) dot += Qs[q * QSTRIDE + d] * ks[d];
            g_M[(size_t)bh * Lx + qbase + q] = SCALEF * (rmax[i] - dot * (1.0f / Lx));
        }
    }
}

// ---------------------------------------------------------------------------
// Top-38 selection per bh (iterative max with lowest-index tiebreak)
// ---------------------------------------------------------------------------
__global__ void topk_kernel()
{
    int bh = blockIdx.x;
    int tid = threadIdx.x;
    __shared__ float vals[Lx];
    __shared__ float rv[256];
    __shared__ int ri[256];
    for (int i = tid; i < Lx; i += 256) vals[i] = g_M[(size_t)bh * Lx + i];
    __syncthreads();
    for (int it = 0; it < KTOP; it++) {
        float best = -1e30f;
        int bidx = 0;
        for (int i = tid; i < Lx; i += 256) {
            float v = vals[i];
            if (v > best) { best = v; bidx = i; }
        }
        rv[tid] = best;
        ri[tid] = bidx;
        __syncthreads();
        for (int s = 128; s > 0; s >>= 1) {
            if (tid < s) {
                if (rv[tid + s] > rv[tid] ||
                    (rv[tid + s] == rv[tid] && ri[tid + s] < ri[tid])) {
                    rv[tid] = rv[tid + s];
                    ri[tid] = ri[tid + s];
                }
            }
            __syncthreads();
        }
        if (tid == 0) {
            g_top[bh * KTOP + it] = ri[0];
            vals[ri[0]] = -1e30f;
        }
        __syncthreads();
    }
}

// ---------------------------------------------------------------------------
// Sparse attention, 2 queries per block: halves K/V traffic and QK/PV loads.
// grid (KHALF, BHx); queries i and i+KHALF.
// ---------------------------------------------------------------------------
__global__ __launch_bounds__(256)
void sparse_attn_kernel()
{
    const int bh = blockIdx.y;
    const int i0 = blockIdx.x;
    const int i1 = blockIdx.x + KHALF;
    const int tid = threadIdx.x;
    const int q0 = g_top[bh * KTOP + i0];
    const int q1 = g_top[bh * KTOP + i1];

    __shared__ float sc0[Lx];
    __shared__ float sc1[Lx];
    __shared__ float qrow[2][DHx];
    __shared__ float red[256];

    if (tid < 64) {
        qrow[0][tid] = g_Q[((size_t)bh * Lx + q0) * DHx + tid];
        qrow[1][tid] = g_Q[((size_t)bh * Lx + q1) * DHx + tid];
    }
    __syncthreads();

    const int warp = tid >> 5, lane = tid & 31;
    const float qa0 = qrow[0][lane], qa1 = qrow[0][lane + 32];
    const float qb0 = qrow[1][lane], qb1 = qrow[1][lane + 32];
    for (int k = warp; k < Lx; k += 8) {
        const float* kr = g_K + ((size_t)bh * Lx + k) * DHx;
        float k0 = kr[lane], k1 = kr[lane + 32];
        float pa = k0 * qa0 + k1 * qa1;
        float pb = k0 * qb0 + k1 * qb1;
#pragma unroll
        for (int o = 16; o > 0; o >>= 1) {
            pa += __shfl_xor_sync(0xffffffffu, pa, o);
            pb += __shfl_xor_sync(0xffffffffu, pb, o);
        }
        if (lane == 0) { sc0[k] = pa * SCALEF; sc1[k] = pb * SCALEF; }
    }
    __syncthreads();

    float inv0, inv1;
    // softmax normalize sc0 then sc1
    for (int qq = 0; qq < 2; qq++) {
        float* sc = qq ? sc1 : sc0;
        float mx = -1e30f;
        for (int k = tid; k < Lx; k += 256) mx = fmaxf(mx, sc[k]);
        red[tid] = mx;
        __syncthreads();
        for (int s = 128; s > 0; s >>= 1) {
            if (tid < s) red[tid] = fmaxf(red[tid], red[tid + s]);
            __syncthreads();
        }
        mx = red[0];
        __syncthreads();
        float sum = 0.f;
        for (int k = tid; k < Lx; k += 256) {
            float e = __expf(sc[k] - mx);
            sc[k] = e;
            sum += e;
        }
        red[tid] = sum;
        __syncthreads();
        for (int s = 128; s > 0; s >>= 1) {
            if (tid < s) red[tid] += red[tid + s];
            __syncthreads();
        }
        if (qq == 0) inv0 = 1.0f / red[0]; else inv1 = 1.0f / red[0];
        __syncthreads();
    }

    const int d = tid & 63, s4 = tid >> 6;
    float acc0 = 0.f, acc1 = 0.f;
    for (int k = s4; k < Lx; k += 4) {
        float v = g_V[((size_t)bh * Lx + k) * DHx + d];
        acc0 += sc0[k] * v;
        acc1 += sc1[k] * v;
    }
    __shared__ float red2[2][256];
    red2[0][tid] = acc0;
    red2[1][tid] = acc1;
    __syncthreads();
    if (tid < 64) {
        float vm = g_Vmean[bh * DHx + d];
        float c0 = (red2[0][d] + red2[0][d + 64] + red2[0][d + 128] + red2[0][d + 192]) * inv0;
        float c1 = (red2[1][d] + red2[1][d + 64] + red2[1][d + 128] + red2[1][d + 192]) * inv1;
        g_delta[((size_t)bh * KTOP + i0) * DHx + d] = c0 - vm;
        g_delta[((size_t)bh * KTOP + i1) * DHx + d] = c1 - vm;
    }
}

// ---------------------------------------------------------------------------
__global__ void base_kernel(const float* __restrict__ Wo, const float* __restrict__ bo)
{
    int b = blockIdx.x, j = threadIdx.x;
    float acc = bo[j];
    for (int c = 0; c < Dx; c++) {
        int h = c >> 6, d = c & 63;
        acc += g_Vmean[(b * Hx + h) * DHx + d] * Wo[(size_t)c * Dx + j];
    }
    g_base[b * Dx + j] = acc;
}

__global__ void fill_kernel(float* __restrict__ out)
{
    size_t idx = (size_t)blockIdx.x * blockDim.x + threadIdx.x;
    if (idx < (size_t)Bx * Lx * Dx) {
        int b = (int)(idx / ((size_t)Lx * Dx));
        int j = (int)(idx % Dx);
        out[idx] = g_base[b * Dx + j];
    }
}

__global__ void scatter_kernel(const float* __restrict__ Wo, float* __restrict__ out)
{
    const int bh = blockIdx.y;
    const int i = blockIdx.x;
    const int j = threadIdx.x;  // 512
    const int b = bh >> 3, h = bh & 7;
    const int l = g_top[bh * KTOP + i];
    __shared__ float dl[DHx];
    if (j < 64) dl[j] = g_delta[((size_t)bh * KTOP + i) * DHx + j];
    __syncthreads();
    float acc = 0.f;
#pragma unroll 16
    for (int d = 0; d < 64; d++) acc += dl[d] * Wo[(size_t)(h * 64 + d) * Dx + j];
    atomicAdd(&out[((size_t)b * Lx + l) * Dx + j], acc);
}

// ---------------------------------------------------------------------------
extern "C" void kernel_launch(void* const* d_in, const int* in_sizes, int n_in,
                              void* d_out, int out_size)
{
    const float* x  = (const float*)d_in[0];
    const float* Wq = (const float*)d_in[1];
    const float* bq = (const float*)d_in[2];
    const float* Wk = (const float*)d_in[3];
    const float* bk = (const float*)d_in[4];
    const float* Wv = (const float*)d_in[5];
    const float* bv = (const float*)d_in[6];
    const float* Wo = (const float*)d_in[7];
    const float* bo = (const float*)d_in[8];
    float* out = (float*)d_out;

    (void)in_sizes; (void)n_in; (void)out_size;

    const int score_smem = 2 * 128 * QSTRIDE * (int)sizeof(float);
    cudaFuncSetAttribute(score_kernel, cudaFuncAttributeMaxDynamicSharedMemorySize,
                         score_smem);

    float* gQ; cudaGetSymbolAddress((void**)&gQ, g_Q);
    float* gK; cudaGetSymbolAddress((void**)&gK, g_K);
    float* gV; cudaGetSymbolAddress((void**)&gV, g_V);

    dim3 pg(Dx / 128, (Bx * Lx) / 128);  // (4, 64)
    proj_kernel<<<pg, 256>>>(x, Wq, bq, gQ);
    proj_kernel<<<pg, 256>>>(x, Wk, bk, gK);
    proj_kernel<<<pg, 256>>>(x, Wv, bv, gV);

    zero_sums_kernel<<<(BHx * DHx + 255) / 256, 256>>>();
    partial_sums_kernel<<<dim3(BHx, 16), 256>>>();
    finalize_vmean_kernel<<<(BHx * DHx + 255) / 256, 256>>>();

    score_kernel<<<dim3(Lx / 128, BHx), 256, score_smem>>>();

    topk_kernel<<<BHx, 256>>>();

    sparse_attn_kernel<<<dim3(KHALF, BHx), 256>>>();

    base_kernel<<<Bx, Dx>>>(Wo, bo);
    fill_kernel<<<(Bx * Lx * Dx + 255) / 256, 256>>>(out);
    scatter_kernel<<<dim3(KTOP, BHx), Dx>>>(Wo, out);
}

// round 5
// speedup vs baseline: 1.0011x; 1.0011x over previous
#include <cuda_runtime.h>
#include <math.h>

#define Bx 4
#define Lx 2048
#define Dx 512
#define Hx 8
#define DHx 64
#define BHx 32
#define KTOP 38
#define KHALF 19
#define SCALEF 0.125f
#define QSTRIDE 66   // == 2 mod 32 -> conflict-free b[j] LDS, float2-aligned

// ---------------- scratch (device globals; no allocation allowed) ----------
__device__ float g_Q[BHx * Lx * DHx];      // 16 MB, [bh][l][d]
__device__ float g_K[BHx * Lx * DHx];      // 16 MB
__device__ float g_V[BHx * Lx * DHx];      // 16 MB
__device__ float g_M[BHx * Lx];            // sparsity measure per (bh, q)
__device__ int   g_top[BHx * KTOP];
__device__ float g_Ksum[BHx * DHx];        // raw column sum of K
__device__ float g_Vsum[BHx * DHx];        // raw column sum of V
__device__ float g_Vmean[BHx * DHx];
__device__ float g_delta[BHx * KTOP * DHx];  // ctx_sparse - Vmean
__device__ float g_base[Bx * Dx];            // (cat Vmean) @ Wo + bo per batch

// ---------------------------------------------------------------------------
// Projection GEMM: Y = X[8192,512] @ W[512,512] + b, output in [bh][l][d] layout.
// ---------------------------------------------------------------------------
__global__ __launch_bounds__(256)
void proj_kernel(const float* __restrict__ X, const float* __restrict__ W,
                 const float* __restrict__ bias, float* __restrict__ out)
{
    __shared__ float As[16][132];  // [k][m], padded
    __shared__ float Bs[16][128];  // [k][n]

    const int tid = threadIdx.x;
    const int tx = tid & 15;
    const int ty = tid >> 4;
    const int mbase = blockIdx.y * 128;
    const int nbase = blockIdx.x * 128;

    float acc[8][8];
#pragma unroll
    for (int i = 0; i < 8; i++)
#pragma unroll
        for (int j = 0; j < 8; j++) acc[i][j] = 0.f;

    for (int kt = 0; kt < Dx; kt += 16) {
#pragma unroll
        for (int it = 0; it < 2; it++) {
            int lin = tid + it * 256;          // 0..511
            int m = lin >> 2;                  // 0..127
            int c4 = lin & 3;                  // 0..3
            float4 v = *reinterpret_cast<const float4*>(
                X + (size_t)(mbase + m) * Dx + kt + c4 * 4);
            As[c4 * 4 + 0][m] = v.x;
            As[c4 * 4 + 1][m] = v.y;
            As[c4 * 4 + 2][m] = v.z;
            As[c4 * 4 + 3][m] = v.w;
        }
#pragma unroll
        for (int it = 0; it < 2; it++) {
            int lin = tid + it * 256;
            int n4 = lin & 31;
            int k = lin >> 5;
            float4 v = *reinterpret_cast<const float4*>(
                W + (size_t)(kt + k) * Dx + nbase + n4 * 4);
            *reinterpret_cast<float4*>(&Bs[k][n4 * 4]) = v;
        }
        __syncthreads();
#pragma unroll
        for (int kk = 0; kk < 16; kk++) {
            float a[8], b[8];
#pragma unroll
            for (int i = 0; i < 8; i++) a[i] = As[kk][ty + 16 * i];
#pragma unroll
            for (int j = 0; j < 8; j++) b[j] = Bs[kk][tx + 16 * j];
#pragma unroll
            for (int i = 0; i < 8; i++)
#pragma unroll
                for (int j = 0; j < 8; j++) acc[i][j] += a[i] * b[j];
        }
        __syncthreads();
    }

#pragma unroll
    for (int i = 0; i < 8; i++) {
        int r = mbase + ty + 16 * i;
        int b = r >> 11;
        int l = r & 2047;
#pragma unroll
        for (int j = 0; j < 8; j++) {
            int c = nbase + tx + 16 * j;
            int h = c >> 6;
            int d = c & 63;
            out[(((size_t)(b * Hx + h)) * Lx + l) * DHx + d] = acc[i][j] + bias[c];
        }
    }
}

// ---------------------------------------------------------------------------
// Parallel K column-sum / V column-sum: grid (BHx, 16), 128 rows per block.
// ---------------------------------------------------------------------------
__global__ void zero_sums_kernel()
{
    int i = blockIdx.x * blockDim.x + threadIdx.x;
    if (i < BHx * DHx) { g_Ksum[i] = 0.f; g_Vsum[i] = 0.f; }
}

__global__ void partial_sums_kernel()
{
    const int bh = blockIdx.x;
    const int kb = blockIdx.y * 128;
    const int tid = threadIdx.x;
    const int d = tid & 63, s = tid >> 6;  // 4 slices of 32 rows
    float ks = 0.f, vs = 0.f;
    for (int k = kb + s; k < kb + 128; k += 4) {
        ks += g_K[((size_t)bh * Lx + k) * DHx + d];
        vs += g_V[((size_t)bh * Lx + k) * DHx + d];
    }
    __shared__ float red[2][256];
    red[0][tid] = ks;
    red[1][tid] = vs;
    __syncthreads();
    if (tid < 64) {
        float a = red[0][d] + red[0][d + 64] + red[0][d + 128] + red[0][d + 192];
        float b = red[1][d] + red[1][d + 64] + red[1][d + 128] + red[1][d + 192];
        atomicAdd(&g_Ksum[bh * DHx + d], a);
        atomicAdd(&g_Vsum[bh * DHx + d], b);
    }
}

__global__ void finalize_vmean_kernel()
{
    int i = blockIdx.x * blockDim.x + threadIdx.x;
    if (i < BHx * DHx) g_Vmean[i] = g_Vsum[i] * (1.0f / Lx);
}

// ---------------------------------------------------------------------------
// Row stats: M[bh][q] = SCALE * ( max_k Q·K[k]  -  Q·Ksum / L )
// Tiles [row][d] with stride 66 -> conflict-free LDS on the b[j] stream.
// Dynamic smem: 2 * 128 * 66 * 4 = 67584 bytes.
// ---------------------------------------------------------------------------
__global__ __launch_bounds__(256)
void score_kernel()
{
    extern __shared__ float sm[];
    float* Qs = sm;                    // 128 rows, stride QSTRIDE
    float* Ks = sm + 128 * QSTRIDE;

    const int bh = blockIdx.y;
    const int qbase = blockIdx.x * 128;
    const int tid = threadIdx.x;
    const int tx = tid & 15;
    const int ty = tid >> 4;

    const float* Qg = g_Q + ((size_t)bh * Lx + qbase) * DHx;
#pragma unroll
    for (int it = 0; it < 8; it++) {
        int lin = tid + it * 256;
        int c4 = lin & 15, r = lin >> 4;
        float4 v = *reinterpret_cast<const float4*>(Qg + r * 64 + c4 * 4);
        float* p = Qs + r * QSTRIDE + c4 * 4;
        *reinterpret_cast<float2*>(p)     = make_float2(v.x, v.y);
        *reinterpret_cast<float2*>(p + 2) = make_float2(v.z, v.w);
    }

    float rmax[8];
#pragma unroll
    for (int i = 0; i < 8; i++) rmax[i] = -1e30f;

    for (int kb = 0; kb < Lx; kb += 128) {
        __syncthreads();
        const float* Kg = g_K + ((size_t)bh * Lx + kb) * DHx;
#pragma unroll
        for (int it = 0; it < 8; it++) {
            int lin = tid + it * 256;
            int c4 = lin & 15, r = lin >> 4;
            float4 v = *reinterpret_cast<const float4*>(Kg + r * 64 + c4 * 4);
            float* p = Ks + r * QSTRIDE + c4 * 4;
            *reinterpret_cast<float2*>(p)     = make_float2(v.x, v.y);
            *reinterpret_cast<float2*>(p + 2) = make_float2(v.z, v.w);
        }
        __syncthreads();

        float acc[8][8];
#pragma unroll
        for (int i = 0; i < 8; i++)
#pragma unroll
            for (int j = 0; j < 8; j++) acc[i][j] = 0.f;

#pragma unroll 8
        for (int d = 0; d < 64; d++) {
            float a[8], b[8];
#pragma unroll
            for (int i = 0; i < 8; i++) a[i] = Qs[(ty + 16 * i) * QSTRIDE + d];
#pragma unroll
            for (int j = 0; j < 8; j++) b[j] = Ks[(tx + 16 * j) * QSTRIDE + d];
#pragma unroll
            for (int i = 0; i < 8; i++)
#pragma unroll
                for (int j = 0; j < 8; j++) acc[i][j] += a[i] * b[j];
        }
#pragma unroll
        for (int i = 0; i < 8; i++) {
            float m = acc[i][0];
#pragma unroll
            for (int j = 1; j < 8; j++) m = fmaxf(m, acc[i][j]);
            rmax[i] = fmaxf(rmax[i], m);
        }
    }

#pragma unroll
    for (int i = 0; i < 8; i++) {
        float m = rmax[i];
        m = fmaxf(m, __shfl_xor_sync(0xffffffffu, m, 1));
        m = fmaxf(m, __shfl_xor_sync(0xffffffffu, m, 2));
        m = fmaxf(m, __shfl_xor_sync(0xffffffffu, m, 4));
        m = fmaxf(m, __shfl_xor_sync(0xffffffffu, m, 8));
        rmax[i] = m;
    }

    if (tx == 0) {
        const float* ks = g_Ksum + bh * DHx;
#pragma unroll
        for (int i = 0; i < 8; i++) {
            int q = ty + 16 * i;
            float dot = 0.f;
#pragma unroll 16
            for (int d = 0; d < 64; d++) dot += Qs[q * QSTRIDE + d] * ks[d];
            g_M[(size_t)bh * Lx + qbase + q] = SCALEF * (rmax[i] - dot * (1.0f / Lx));
        }
    }
}

// ---------------------------------------------------------------------------
// Top-38 selection per bh (iterative max with lowest-index tiebreak)
// ---------------------------------------------------------------------------
__global__ void topk_kernel()
{
    int bh = blockIdx.x;
    int tid = threadIdx.x;
    __shared__ float vals[Lx];
    __shared__ float rv[256];
    __shared__ int ri[256];
    for (int i = tid; i < Lx; i += 256) vals[i] = g_M[(size_t)bh * Lx + i];
    __syncthreads();
    for (int it = 0; it < KTOP; it++) {
        float best = -1e30f;
        int bidx = 0;
        for (int i = tid; i < Lx; i += 256) {
            float v = vals[i];
            if (v > best) { best = v; bidx = i; }
        }
        rv[tid] = best;
        ri[tid] = bidx;
        __syncthreads();
        for (int s = 128; s > 0; s >>= 1) {
            if (tid < s) {
                if (rv[tid + s] > rv[tid] ||
                    (rv[tid + s] == rv[tid] && ri[tid + s] < ri[tid])) {
                    rv[tid] = rv[tid + s];
                    ri[tid] = ri[tid + s];
                }
            }
            __syncthreads();
        }
        if (tid == 0) {
            g_top[bh * KTOP + it] = ri[0];
            vals[ri[0]] = -1e30f;
        }
        __syncthreads();
    }
}

// ---------------------------------------------------------------------------
// Sparse attention, 2 queries per block: halves K/V traffic and QK/PV loads.
// grid (KHALF, BHx); queries i and i+KHALF.
// ---------------------------------------------------------------------------
__global__ __launch_bounds__(256)
void sparse_attn_kernel()
{
    const int bh = blockIdx.y;
    const int i0 = blockIdx.x;
    const int i1 = blockIdx.x + KHALF;
    const int tid = threadIdx.x;
    const int q0 = g_top[bh * KTOP + i0];
    const int q1 = g_top[bh * KTOP + i1];

    __shared__ float sc0[Lx];
    __shared__ float sc1[Lx];
    __shared__ float qrow[2][DHx];
    __shared__ float red[256];

    if (tid < 64) {
        qrow[0][tid] = g_Q[((size_t)bh * Lx + q0) * DHx + tid];
        qrow[1][tid] = g_Q[((size_t)bh * Lx + q1) * DHx + tid];
    }
    __syncthreads();

    const int warp = tid >> 5, lane = tid & 31;
    const float qa0 = qrow[0][lane], qa1 = qrow[0][lane + 32];
    const float qb0 = qrow[1][lane], qb1 = qrow[1][lane + 32];
    for (int k = warp; k < Lx; k += 8) {
        const float* kr = g_K + ((size_t)bh * Lx + k) * DHx;
        float k0 = kr[lane], k1 = kr[lane + 32];
        float pa = k0 * qa0 + k1 * qa1;
        float pb = k0 * qb0 + k1 * qb1;
#pragma unroll
        for (int o = 16; o > 0; o >>= 1) {
            pa += __shfl_xor_sync(0xffffffffu, pa, o);
            pb += __shfl_xor_sync(0xffffffffu, pb, o);
        }
        if (lane == 0) { sc0[k] = pa * SCALEF; sc1[k] = pb * SCALEF; }
    }
    __syncthreads();

    float inv0, inv1;
    // softmax normalize sc0 then sc1
    for (int qq = 0; qq < 2; qq++) {
        float* sc = qq ? sc1 : sc0;
        float mx = -1e30f;
        for (int k = tid; k < Lx; k += 256) mx = fmaxf(mx, sc[k]);
        red[tid] = mx;
        __syncthreads();
        for (int s = 128; s > 0; s >>= 1) {
            if (tid < s) red[tid] = fmaxf(red[tid], red[tid + s]);
            __syncthreads();
        }
        mx = red[0];
        __syncthreads();
        float sum = 0.f;
        for (int k = tid; k < Lx; k += 256) {
            float e = __expf(sc[k] - mx);
            sc[k] = e;
            sum += e;
        }
        red[tid] = sum;
        __syncthreads();
        for (int s = 128; s > 0; s >>= 1) {
            if (tid < s) red[tid] += red[tid + s];
            __syncthreads();
        }
        if (qq == 0) inv0 = 1.0f / red[0]; else inv1 = 1.0f / red[0];
        __syncthreads();
    }

    const int d = tid & 63, s4 = tid >> 6;
    float acc0 = 0.f, acc1 = 0.f;
    for (int k = s4; k < Lx; k += 4) {
        float v = g_V[((size_t)bh * Lx + k) * DHx + d];
        acc0 += sc0[k] * v;
        acc1 += sc1[k] * v;
    }
    __shared__ float red2[2][256];
    red2[0][tid] = acc0;
    red2[1][tid] = acc1;
    __syncthreads();
    if (tid < 64) {
        float vm = g_Vmean[bh * DHx + d];
        float c0 = (red2[0][d] + red2[0][d + 64] + red2[0][d + 128] + red2[0][d + 192]) * inv0;
        float c1 = (red2[1][d] + red2[1][d + 64] + red2[1][d + 128] + red2[1][d + 192]) * inv1;
        g_delta[((size_t)bh * KTOP + i0) * DHx + d] = c0 - vm;
        g_delta[((size_t)bh * KTOP + i1) * DHx + d] = c1 - vm;
    }
}

// ---------------------------------------------------------------------------
__global__ void base_kernel(const float* __restrict__ Wo, const float* __restrict__ bo)
{
    int b = blockIdx.x, j = threadIdx.x;
    float acc = bo[j];
    for (int c = 0; c < Dx; c++) {
        int h = c >> 6, d = c & 63;
        acc += g_Vmean[(b * Hx + h) * DHx + d] * Wo[(size_t)c * Dx + j];
    }
    g_base[b * Dx + j] = acc;
}

__global__ void fill_kernel(float* __restrict__ out)
{
    size_t idx = (size_t)blockIdx.x * blockDim.x + threadIdx.x;
    if (idx < (size_t)Bx * Lx * Dx) {
        int b = (int)(idx / ((size_t)Lx * Dx));
        int j = (int)(idx % Dx);
        out[idx] = g_base[b * Dx + j];
    }
}

__global__ void scatter_kernel(const float* __restrict__ Wo, float* __restrict__ out)
{
    const int bh = blockIdx.y;
    const int i = blockIdx.x;
    const int j = threadIdx.x;  // 512
    const int b = bh >> 3, h = bh & 7;
    const int l = g_top[bh * KTOP + i];
    __shared__ float dl[DHx];
    if (j < 64) dl[j] = g_delta[((size_t)bh * KTOP + i) * DHx + j];
    __syncthreads();
    float acc = 0.f;
#pragma unroll 16
    for (int d = 0; d < 64; d++) acc += dl[d] * Wo[(size_t)(h * 64 + d) * Dx + j];
    atomicAdd(&out[((size_t)b * Lx + l) * Dx + j], acc);
}

// ---------------------------------------------------------------------------
extern "C" void kernel_launch(void* const* d_in, const int* in_sizes, int n_in,
                              void* d_out, int out_size)
{
    const float* x  = (const float*)d_in[0];
    const float* Wq = (const float*)d_in[1];
    const float* bq = (const float*)d_in[2];
    const float* Wk = (const float*)d_in[3];
    const float* bk = (const float*)d_in[4];
    const float* Wv = (const float*)d_in[5];
    const float* bv = (const float*)d_in[6];
    const float* Wo = (const float*)d_in[7];
    const float* bo = (const float*)d_in[8];
    float* out = (float*)d_out;

    (void)in_sizes; (void)n_in; (void)out_size;

    const int score_smem = 2 * 128 * QSTRIDE * (int)sizeof(float);
    cudaFuncSetAttribute(score_kernel, cudaFuncAttributeMaxDynamicSharedMemorySize,
                         score_smem);

    float* gQ; cudaGetSymbolAddress((void**)&gQ, g_Q);
    float* gK; cudaGetSymbolAddress((void**)&gK, g_K);
    float* gV; cudaGetSymbolAddress((void**)&gV, g_V);

    dim3 pg(Dx / 128, (Bx * Lx) / 128);  // (4, 64)
    proj_kernel<<<pg, 256>>>(x, Wq, bq, gQ);
    proj_kernel<<<pg, 256>>>(x, Wk, bk, gK);
    proj_kernel<<<pg, 256>>>(x, Wv, bv, gV);

    zero_sums_kernel<<<(BHx * DHx + 255) / 256, 256>>>();
    partial_sums_kernel<<<dim3(BHx, 16), 256>>>();
    finalize_vmean_kernel<<<(BHx * DHx + 255) / 256, 256>>>();

    score_kernel<<<dim3(Lx / 128, BHx), 256, score_smem>>>();

    topk_kernel<<<BHx, 256>>>();

    sparse_attn_kernel<<<dim3(KHALF, BHx), 256>>>();

    base_kernel<<<Bx, Dx>>>(Wo, bo);
    fill_kernel<<<(Bx * Lx * Dx + 255) / 256, 256>>>(out);
    scatter_kernel<<<dim3(KTOP, BHx), Dx>>>(Wo, out);
}

// round 6
// speedup vs baseline: 1.1027x; 1.1015x over previous
#include <cuda_runtime.h>
#include <math.h>

#define Bx 4
#define Lx 2048
#define Dx 512
#define Hx 8
#define DHx 64
#define BHx 32
#define KTOP 38
#define KHALF 19
#define SCALEF 0.125f
#define QSTRIDE 66    // == 2 mod 32 -> conflict-free scalar a-loads
#define TSTRIDE 130   // Ks_T row stride (even -> 8B-aligned b64 loads)

typedef unsigned long long ull;

__device__ __forceinline__ ull fma2(ull a, ull b, ull c) {
    ull d;
    asm("fma.rn.f32x2 %0, %1, %2, %3;" : "=l"(d) : "l"(a), "l"(b), "l"(c));
    return d;
}
__device__ __forceinline__ ull splat2(float x) {
    ull d;
    asm("mov.b64 %0, {%1, %1};" : "=l"(d) : "f"(x));
    return d;
}
__device__ __forceinline__ void unpack2(ull v, float& lo, float& hi) {
    asm("mov.b64 {%0, %1}, %2;" : "=f"(lo), "=f"(hi) : "l"(v));
}

// ---------------- scratch (device globals; no allocation allowed) ----------
__device__ float g_Q[BHx * Lx * DHx];
__device__ float g_K[BHx * Lx * DHx];
__device__ float g_V[BHx * Lx * DHx];
__device__ float g_M[BHx * Lx];
__device__ int   g_top[BHx * KTOP];
__device__ float g_Ksum[BHx * DHx];
__device__ float g_Vsum[BHx * DHx];
__device__ float g_Vmean[BHx * DHx];
__device__ float g_delta[BHx * KTOP * DHx];
__device__ float g_base[Bx * Dx];

// ---------------------------------------------------------------------------
// Projection GEMM with f32x2: Y = X[8192,512] @ W[512,512] + b.
// Thread covers rows ty+16i (i<8), column PAIRS 2tx+32j (j<4).
// ---------------------------------------------------------------------------
__global__ __launch_bounds__(256)
void proj_kernel(const float* __restrict__ X, const float* __restrict__ W,
                 const float* __restrict__ bias, float* __restrict__ out)
{
    __shared__ float As[16][132];  // [k][m], padded
    __shared__ float Bs[16][128];  // [k][n]

    const int tid = threadIdx.x;
    const int tx = tid & 15;
    const int ty = tid >> 4;
    const int mbase = blockIdx.y * 128;
    const int nbase = blockIdx.x * 128;

    ull acc[8][4];
#pragma unroll
    for (int i = 0; i < 8; i++)
#pragma unroll
        for (int j = 0; j < 4; j++) acc[i][j] = 0ull;

    for (int kt = 0; kt < Dx; kt += 16) {
#pragma unroll
        for (int it = 0; it < 2; it++) {
            int lin = tid + it * 256;          // 0..511
            int m = lin >> 2;
            int c4 = lin & 3;
            float4 v = *reinterpret_cast<const float4*>(
                X + (size_t)(mbase + m) * Dx + kt + c4 * 4);
            As[c4 * 4 + 0][m] = v.x;
            As[c4 * 4 + 1][m] = v.y;
            As[c4 * 4 + 2][m] = v.z;
            As[c4 * 4 + 3][m] = v.w;
        }
#pragma unroll
        for (int it = 0; it < 2; it++) {
            int lin = tid + it * 256;
            int n4 = lin & 31;
            int k = lin >> 5;
            float4 v = *reinterpret_cast<const float4*>(
                W + (size_t)(kt + k) * Dx + nbase + n4 * 4);
            *reinterpret_cast<float4*>(&Bs[k][n4 * 4]) = v;
        }
        __syncthreads();
#pragma unroll
        for (int kk = 0; kk < 16; kk++) {
            ull a2[8], b2[4];
#pragma unroll
            for (int i = 0; i < 8; i++) a2[i] = splat2(As[kk][ty + 16 * i]);
#pragma unroll
            for (int j = 0; j < 4; j++)
                b2[j] = *reinterpret_cast<const ull*>(&Bs[kk][2 * tx + 32 * j]);
#pragma unroll
            for (int i = 0; i < 8; i++)
#pragma unroll
                for (int j = 0; j < 4; j++) acc[i][j] = fma2(a2[i], b2[j], acc[i][j]);
        }
        __syncthreads();
    }

#pragma unroll
    for (int i = 0; i < 8; i++) {
        int r = mbase + ty + 16 * i;
        int b = r >> 11;
        int l = r & 2047;
#pragma unroll
        for (int j = 0; j < 4; j++) {
            float lo, hi;
            unpack2(acc[i][j], lo, hi);
            int c0 = nbase + 2 * tx + 32 * j;
#pragma unroll
            for (int u = 0; u < 2; u++) {
                int c = c0 + u;
                int h = c >> 6;
                int d = c & 63;
                out[(((size_t)(b * Hx + h)) * Lx + l) * DHx + d] =
                    (u ? hi : lo) + bias[c];
            }
        }
    }
}

// ---------------------------------------------------------------------------
// K / V column sums (parallel over 16 row-chunks), then V mean.
// ---------------------------------------------------------------------------
__global__ void zero_sums_kernel()
{
    int i = blockIdx.x * blockDim.x + threadIdx.x;
    if (i < BHx * DHx) { g_Ksum[i] = 0.f; g_Vsum[i] = 0.f; }
}

__global__ void partial_sums_kernel()
{
    const int bh = blockIdx.x;
    const int kb = blockIdx.y * 128;
    const int tid = threadIdx.x;
    const int d = tid & 63, s = tid >> 6;
    float ks = 0.f, vs = 0.f;
    for (int k = kb + s; k < kb + 128; k += 4) {
        ks += g_K[((size_t)bh * Lx + k) * DHx + d];
        vs += g_V[((size_t)bh * Lx + k) * DHx + d];
    }
    __shared__ float red[2][256];
    red[0][tid] = ks;
    red[1][tid] = vs;
    __syncthreads();
    if (tid < 64) {
        float a = red[0][d] + red[0][d + 64] + red[0][d + 128] + red[0][d + 192];
        float b = red[1][d] + red[1][d + 64] + red[1][d + 128] + red[1][d + 192];
        atomicAdd(&g_Ksum[bh * DHx + d], a);
        atomicAdd(&g_Vsum[bh * DHx + d], b);
    }
}

__global__ void finalize_vmean_kernel()
{
    int i = blockIdx.x * blockDim.x + threadIdx.x;
    if (i < BHx * DHx) g_Vmean[i] = g_Vsum[i] * (1.0f / Lx);
}

// ---------------------------------------------------------------------------
// Row stats with f32x2: M[bh][q] = SCALE * ( max_k Q·K[k] - Q·Ksum / L ).
// Qs[row][d] stride 66 (scalar a + splat); K tile stored TRANSPOSED as
// Ks_T[d][krow] stride 130 so b-pairs are LDS.64. Transpose stores are
// bank-conflict-free and gmem loads stay coalesced (4 rows x 8 float2 / warp).
// Dynamic smem: 128*66*4 + 64*130*4 = 67072 bytes.
// ---------------------------------------------------------------------------
__global__ __launch_bounds__(256)
void score_kernel()
{
    extern __shared__ float sm[];
    float* Qs = sm;                         // [128][QSTRIDE]
    float* KsT = sm + 128 * QSTRIDE;        // [64][TSTRIDE]

    const int bh = blockIdx.y;
    const int qbase = blockIdx.x * 128;
    const int tid = threadIdx.x;
    const int tx = tid & 15;
    const int ty = tid >> 4;
    const int lane = tid & 31;
    const int w = tid >> 5;
    const int rsub = lane >> 3;      // 0..3
    const int c2lo = lane & 7;       // 0..7

    const float* Qg = g_Q + ((size_t)bh * Lx + qbase) * DHx;
#pragma unroll
    for (int it = 0; it < 8; it++) {
        int lin = tid + it * 256;
        int c4 = lin & 15, r = lin >> 4;
        float4 v = *reinterpret_cast<const float4*>(Qg + r * 64 + c4 * 4);
        float* p = Qs + r * QSTRIDE + c4 * 4;
        *reinterpret_cast<float2*>(p)     = make_float2(v.x, v.y);
        *reinterpret_cast<float2*>(p + 2) = make_float2(v.z, v.w);
    }

    float rmax[8];
#pragma unroll
    for (int i = 0; i < 8; i++) rmax[i] = -1e30f;

    for (int kb = 0; kb < Lx; kb += 128) {
        __syncthreads();
        const float* Kg = g_K + ((size_t)bh * Lx + kb) * DHx;
        // transposed fill: r = rsub + 4*(w + 8*(q&3)), c2 = c2lo + 8*(q>>2)
#pragma unroll
        for (int q = 0; q < 16; q++) {
            int r  = rsub + 4 * (w + 8 * (q & 3));
            int c2 = c2lo + 8 * (q >> 2);
            float2 v = *reinterpret_cast<const float2*>(Kg + r * 64 + 2 * c2);
            KsT[(2 * c2 + 0) * TSTRIDE + r] = v.x;
            KsT[(2 * c2 + 1) * TSTRIDE + r] = v.y;
        }
        __syncthreads();

        ull acc[8][4];
#pragma unroll
        for (int i = 0; i < 8; i++)
#pragma unroll
            for (int j = 0; j < 4; j++) acc[i][j] = 0ull;

#pragma unroll 4
        for (int d = 0; d < 64; d++) {
            ull a2[8], b2[4];
#pragma unroll
            for (int i = 0; i < 8; i++)
                a2[i] = splat2(Qs[(ty + 16 * i) * QSTRIDE + d]);
#pragma unroll
            for (int j = 0; j < 4; j++)
                b2[j] = *reinterpret_cast<const ull*>(
                            &KsT[d * TSTRIDE + 2 * tx + 32 * j]);
#pragma unroll
            for (int i = 0; i < 8; i++)
#pragma unroll
                for (int j = 0; j < 4; j++) acc[i][j] = fma2(a2[i], b2[j], acc[i][j]);
        }

#pragma unroll
        for (int i = 0; i < 8; i++) {
            float m = rmax[i];
#pragma unroll
            for (int j = 0; j < 4; j++) {
                float lo, hi;
                unpack2(acc[i][j], lo, hi);
                m = fmaxf(m, fmaxf(lo, hi));
            }
            rmax[i] = m;
        }
    }

#pragma unroll
    for (int i = 0; i < 8; i++) {
        float m = rmax[i];
        m = fmaxf(m, __shfl_xor_sync(0xffffffffu, m, 1));
        m = fmaxf(m, __shfl_xor_sync(0xffffffffu, m, 2));
        m = fmaxf(m, __shfl_xor_sync(0xffffffffu, m, 4));
        m = fmaxf(m, __shfl_xor_sync(0xffffffffu, m, 8));
        rmax[i] = m;
    }

    if (tx == 0) {
        const float* ks = g_Ksum + bh * DHx;
#pragma unroll
        for (int i = 0; i < 8; i++) {
            int q = ty + 16 * i;
            float dot = 0.f;
#pragma unroll 16
            for (int d = 0; d < 64; d++) dot += Qs[q * QSTRIDE + d] * ks[d];
            g_M[(size_t)bh * Lx + qbase + q] = SCALEF * (rmax[i] - dot * (1.0f / Lx));
        }
    }
}

// ---------------------------------------------------------------------------
// Top-38 selection per bh (iterative max with lowest-index tiebreak)
// ---------------------------------------------------------------------------
__global__ void topk_kernel()
{
    int bh = blockIdx.x;
    int tid = threadIdx.x;
    __shared__ float vals[Lx];
    __shared__ float rv[256];
    __shared__ int ri[256];
    for (int i = tid; i < Lx; i += 256) vals[i] = g_M[(size_t)bh * Lx + i];
    __syncthreads();
    for (int it = 0; it < KTOP; it++) {
        float best = -1e30f;
        int bidx = 0;
        for (int i = tid; i < Lx; i += 256) {
            float v = vals[i];
            if (v > best) { best = v; bidx = i; }
        }
        rv[tid] = best;
        ri[tid] = bidx;
        __syncthreads();
        for (int s = 128; s > 0; s >>= 1) {
            if (tid < s) {
                if (rv[tid + s] > rv[tid] ||
                    (rv[tid + s] == rv[tid] && ri[tid + s] < ri[tid])) {
                    rv[tid] = rv[tid + s];
                    ri[tid] = ri[tid + s];
                }
            }
            __syncthreads();
        }
        if (tid == 0) {
            g_top[bh * KTOP + it] = ri[0];
            vals[ri[0]] = -1e30f;
        }
        __syncthreads();
    }
}

// ---------------------------------------------------------------------------
// Sparse attention, 2 queries per block.
// ---------------------------------------------------------------------------
__global__ __launch_bounds__(256)
void sparse_attn_kernel()
{
    const int bh = blockIdx.y;
    const int i0 = blockIdx.x;
    const int i1 = blockIdx.x + KHALF;
    const int tid = threadIdx.x;
    const int q0 = g_top[bh * KTOP + i0];
    const int q1 = g_top[bh * KTOP + i1];

    __shared__ float sc0[Lx];
    __shared__ float sc1[Lx];
    __shared__ float qrow[2][DHx];
    __shared__ float red[256];

    if (tid < 64) {
        qrow[0][tid] = g_Q[((size_t)bh * Lx + q0) * DHx + tid];
        qrow[1][tid] = g_Q[((size_t)bh * Lx + q1) * DHx + tid];
    }
    __syncthreads();

    const int warp = tid >> 5, lane = tid & 31;
    const float qa0 = qrow[0][lane], qa1 = qrow[0][lane + 32];
    const float qb0 = qrow[1][lane], qb1 = qrow[1][lane + 32];
    for (int k = warp; k < Lx; k += 8) {
        const float* kr = g_K + ((size_t)bh * Lx + k) * DHx;
        float k0 = kr[lane], k1 = kr[lane + 32];
        float pa = k0 * qa0 + k1 * qa1;
        float pb = k0 * qb0 + k1 * qb1;
#pragma unroll
        for (int o = 16; o > 0; o >>= 1) {
            pa += __shfl_xor_sync(0xffffffffu, pa, o);
            pb += __shfl_xor_sync(0xffffffffu, pb, o);
        }
        if (lane == 0) { sc0[k] = pa * SCALEF; sc1[k] = pb * SCALEF; }
    }
    __syncthreads();

    float inv0, inv1;
    for (int qq = 0; qq < 2; qq++) {
        float* sc = qq ? sc1 : sc0;
        float mx = -1e30f;
        for (int k = tid; k < Lx; k += 256) mx = fmaxf(mx, sc[k]);
        red[tid] = mx;
        __syncthreads();
        for (int s = 128; s > 0; s >>= 1) {
            if (tid < s) red[tid] = fmaxf(red[tid], red[tid + s]);
            __syncthreads();
        }
        mx = red[0];
        __syncthreads();
        float sum = 0.f;
        for (int k = tid; k < Lx; k += 256) {
            float e = __expf(sc[k] - mx);
            sc[k] = e;
            sum += e;
        }
        red[tid] = sum;
        __syncthreads();
        for (int s = 128; s > 0; s >>= 1) {
            if (tid < s) red[tid] += red[tid + s];
            __syncthreads();
        }
        if (qq == 0) inv0 = 1.0f / red[0]; else inv1 = 1.0f / red[0];
        __syncthreads();
    }

    const int d = tid & 63, s4 = tid >> 6;
    float acc0 = 0.f, acc1 = 0.f;
    for (int k = s4; k < Lx; k += 4) {
        float v = g_V[((size_t)bh * Lx + k) * DHx + d];
        acc0 += sc0[k] * v;
        acc1 += sc1[k] * v;
    }
    __shared__ float red2[2][256];
    red2[0][tid] = acc0;
    red2[1][tid] = acc1;
    __syncthreads();
    if (tid < 64) {
        float vm = g_Vmean[bh * DHx + d];
        float c0 = (red2[0][d] + red2[0][d + 64] + red2[0][d + 128] + red2[0][d + 192]) * inv0;
        float c1 = (red2[1][d] + red2[1][d + 64] + red2[1][d + 128] + red2[1][d + 192]) * inv1;
        g_delta[((size_t)bh * KTOP + i0) * DHx + d] = c0 - vm;
        g_delta[((size_t)bh * KTOP + i1) * DHx + d] = c1 - vm;
    }
}

// ---------------------------------------------------------------------------
__global__ void base_kernel(const float* __restrict__ Wo, const float* __restrict__ bo)
{
    int b = blockIdx.x, j = threadIdx.x;
    float acc = bo[j];
    for (int c = 0; c < Dx; c++) {
        int h = c >> 6, d = c & 63;
        acc += g_Vmean[(b * Hx + h) * DHx + d] * Wo[(size_t)c * Dx + j];
    }
    g_base[b * Dx + j] = acc;
}

__global__ void fill_kernel(float* __restrict__ out)
{
    size_t idx = (size_t)blockIdx.x * blockDim.x + threadIdx.x;
    if (idx < (size_t)Bx * Lx * Dx) {
        int b = (int)(idx / ((size_t)Lx * Dx));
        int j = (int)(idx % Dx);
        out[idx] = g_base[b * Dx + j];
    }
}

__global__ void scatter_kernel(const float* __restrict__ Wo, float* __restrict__ out)
{
    const int bh = blockIdx.y;
    const int i = blockIdx.x;
    const int j = threadIdx.x;  // 512
    const int b = bh >> 3, h = bh & 7;
    const int l = g_top[bh * KTOP + i];
    __shared__ float dl[DHx];
    if (j < 64) dl[j] = g_delta[((size_t)bh * KTOP + i) * DHx + j];
    __syncthreads();
    float acc = 0.f;
#pragma unroll 16
    for (int d = 0; d < 64; d++) acc += dl[d] * Wo[(size_t)(h * 64 + d) * Dx + j];
    atomicAdd(&out[((size_t)b * Lx + l) * Dx + j], acc);
}

// ---------------------------------------------------------------------------
extern "C" void kernel_launch(void* const* d_in, const int* in_sizes, int n_in,
                              void* d_out, int out_size)
{
    const float* x  = (const float*)d_in[0];
    const float* Wq = (const float*)d_in[1];
    const float* bq = (const float*)d_in[2];
    const float* Wk = (const float*)d_in[3];
    const float* bk = (const float*)d_in[4];
    const float* Wv = (const float*)d_in[5];
    const float* bv = (const float*)d_in[6];
    const float* Wo = (const float*)d_in[7];
    const float* bo = (const float*)d_in[8];
    float* out = (float*)d_out;

    (void)in_sizes; (void)n_in; (void)out_size;

    const int score_smem = (128 * QSTRIDE + 64 * TSTRIDE) * (int)sizeof(float);
    cudaFuncSetAttribute(score_kernel, cudaFuncAttributeMaxDynamicSharedMemorySize,
                         score_smem);

    float* gQ; cudaGetSymbolAddress((void**)&gQ, g_Q);
    float* gK; cudaGetSymbolAddress((void**)&gK, g_K);
    float* gV; cudaGetSymbolAddress((void**)&gV, g_V);

    dim3 pg(Dx / 128, (Bx * Lx) / 128);  // (4, 64)
    proj_kernel<<<pg, 256>>>(x, Wq, bq, gQ);
    proj_kernel<<<pg, 256>>>(x, Wk, bk, gK);
    proj_kernel<<<pg, 256>>>(x, Wv, bv, gV);

    zero_sums_kernel<<<(BHx * DHx + 255) / 256, 256>>>();
    partial_sums_kernel<<<dim3(BHx, 16), 256>>>();
    finalize_vmean_kernel<<<(BHx * DHx + 255) / 256, 256>>>();

    score_kernel<<<dim3(Lx / 128, BHx), 256, score_smem>>>();

    topk_kernel<<<BHx, 256>>>();

    sparse_attn_kernel<<<dim3(KHALF, BHx), 256>>>();

    base_kernel<<<Bx, Dx>>>(Wo, bo);
    fill_kernel<<<(Bx * Lx * Dx + 255) / 256, 256>>>(out);
    scatter_kernel<<<dim3(KTOP, BHx), Dx>>>(Wo, out);
}

// round 8
// speedup vs baseline: 1.1995x; 1.0878x over previous
#include <cuda_runtime.h>
#include <math.h>
#include <stdint.h>

#define Bx 4
#define Lx 2048
#define Dx 512
#define Hx 8
#define DHx 64
#define BHx 32
#define KTOP 38
#define KHALF 19
#define SCALEF 0.125f
#define SSTR 68   // smem row stride: 68 % 32 == 4 -> conflict-free mma fragments

typedef unsigned long long ull;

// ---------------- f32x2 helpers (proj) --------------------------------------
__device__ __forceinline__ ull fma2(ull a, ull b, ull c) {
    ull d;
    asm("fma.rn.f32x2 %0, %1, %2, %3;" : "=l"(d) : "l"(a), "l"(b), "l"(c));
    return d;
}
__device__ __forceinline__ ull splat2(float x) {
    ull d;
    asm("mov.b64 %0, {%1, %1};" : "=l"(d) : "f"(x));
    return d;
}
__device__ __forceinline__ void unpack2(ull v, float& lo, float& hi) {
    asm("mov.b64 {%0, %1}, %2;" : "=f"(lo), "=f"(hi) : "l"(v));
}

// ---------------- tf32 mma.sync helpers (sm_80+ PTX, no arch-suffix gate) ---
__device__ __forceinline__ float tf32r(float x) {
    uint32_t u;
    asm("cvt.rna.tf32.f32 %0, %1;" : "=r"(u) : "f"(x));
    return __uint_as_float(u);
}
__device__ __forceinline__ void mma_tf32(float c[4], const uint32_t a[4],
                                         const uint32_t b[2]) {
    asm volatile(
        "mma.sync.aligned.m16n8k8.row.col.f32.tf32.tf32.f32 "
        "{%0,%1,%2,%3}, {%4,%5,%6,%7}, {%8,%9}, {%0,%1,%2,%3};"
        : "+f"(c[0]), "+f"(c[1]), "+f"(c[2]), "+f"(c[3])
        : "r"(a[0]), "r"(a[1]), "r"(a[2]), "r"(a[3]), "r"(b[0]), "r"(b[1]));
}

// ---------------- scratch (device globals; no allocation allowed) ----------
__device__ float g_Q[BHx * Lx * DHx];
__device__ float g_K[BHx * Lx * DHx];
__device__ float g_V[BHx * Lx * DHx];
__device__ float g_rowmax[BHx * Lx];
__device__ float g_M[BHx * Lx];
__device__ int   g_top[BHx * KTOP];
__device__ float g_Ksum[BHx * DHx];
__device__ float g_Vsum[BHx * DHx];
__device__ float g_delta[BHx * KTOP * DHx];
__device__ float g_base[Bx * Dx];

// ---------------------------------------------------------------------------
// Projection GEMM (f32x2): Y = X[8192,512] @ W[512,512] + b -> [bh][l][d]
// ---------------------------------------------------------------------------
__global__ __launch_bounds__(256)
void proj_kernel(const float* __restrict__ X, const float* __restrict__ W,
                 const float* __restrict__ bias, float* __restrict__ out)
{
    __shared__ float As[16][132];
    __shared__ float Bs[16][128];

    const int tid = threadIdx.x;
    const int tx = tid & 15;
    const int ty = tid >> 4;
    const int mbase = blockIdx.y * 128;
    const int nbase = blockIdx.x * 128;

    ull acc[8][4];
#pragma unroll
    for (int i = 0; i < 8; i++)
#pragma unroll
        for (int j = 0; j < 4; j++) acc[i][j] = 0ull;

    for (int kt = 0; kt < Dx; kt += 16) {
#pragma unroll
        for (int it = 0; it < 2; it++) {
            int lin = tid + it * 256;
            int m = lin >> 2;
            int c4 = lin & 3;
            float4 v = *reinterpret_cast<const float4*>(
                X + (size_t)(mbase + m) * Dx + kt + c4 * 4);
            As[c4 * 4 + 0][m] = v.x;
            As[c4 * 4 + 1][m] = v.y;
            As[c4 * 4 + 2][m] = v.z;
            As[c4 * 4 + 3][m] = v.w;
        }
#pragma unroll
        for (int it = 0; it < 2; it++) {
            int lin = tid + it * 256;
            int n4 = lin & 31;
            int k = lin >> 5;
            float4 v = *reinterpret_cast<const float4*>(
                W + (size_t)(kt + k) * Dx + nbase + n4 * 4);
            *reinterpret_cast<float4*>(&Bs[k][n4 * 4]) = v;
        }
        __syncthreads();
#pragma unroll
        for (int kk = 0; kk < 16; kk++) {
            ull a2[8], b2[4];
#pragma unroll
            for (int i = 0; i < 8; i++) a2[i] = splat2(As[kk][ty + 16 * i]);
#pragma unroll
            for (int j = 0; j < 4; j++)
                b2[j] = *reinterpret_cast<const ull*>(&Bs[kk][2 * tx + 32 * j]);
#pragma unroll
            for (int i = 0; i < 8; i++)
#pragma unroll
                for (int j = 0; j < 4; j++) acc[i][j] = fma2(a2[i], b2[j], acc[i][j]);
        }
        __syncthreads();
    }

#pragma unroll
    for (int i = 0; i < 8; i++) {
        int r = mbase + ty + 16 * i;
        int b = r >> 11;
        int l = r & 2047;
#pragma unroll
        for (int j = 0; j < 4; j++) {
            float lo, hi;
            unpack2(acc[i][j], lo, hi);
            int c0 = nbase + 2 * tx + 32 * j;
#pragma unroll
            for (int u = 0; u < 2; u++) {
                int c = c0 + u;
                int h = c >> 6;
                int d = c & 63;
                out[(((size_t)(b * Hx + h)) * Lx + l) * DHx + d] =
                    (u ? hi : lo) + bias[c];
            }
        }
    }
}

// ---------------------------------------------------------------------------
// score_mma_kernel: rowmax(Q_tile[128,64] @ K^T) via mma.sync tf32, 3xTF32.
// smem: Qhi/Qlo/Khi/Klo each [128][SSTR] fp32 -> 139264 bytes dynamic.
// Warp w owns output rows w*16..w*16+15; C tiles m16n8 over 16 n-tiles.
// ---------------------------------------------------------------------------
__device__ __forceinline__ void convert_fill(const float* __restrict__ src,
                                             float* __restrict__ hi,
                                             float* __restrict__ lo, int tid)
{
#pragma unroll
    for (int i = 0; i < 8; i++) {
        int idx4 = tid + i * 256;          // 0..2047 float4s over [128][64]
        int row = idx4 >> 4;
        int c4 = idx4 & 15;
        float4 v = *reinterpret_cast<const float4*>(src + row * 64 + c4 * 4);
        float4 h, l;
        h.x = tf32r(v.x); l.x = tf32r(v.x - h.x);
        h.y = tf32r(v.y); l.y = tf32r(v.y - h.y);
        h.z = tf32r(v.z); l.z = tf32r(v.z - h.z);
        h.w = tf32r(v.w); l.w = tf32r(v.w - h.w);
        *reinterpret_cast<float4*>(hi + row * SSTR + c4 * 4) = h;
        *reinterpret_cast<float4*>(lo + row * SSTR + c4 * 4) = l;
    }
}

__global__ __launch_bounds__(256)
void score_mma_kernel()
{
    extern __shared__ float sm[];
    float* Qhi = sm;
    float* Qlo = sm + 128 * SSTR;
    float* Khi = sm + 2 * 128 * SSTR;
    float* Klo = sm + 3 * 128 * SSTR;

    const int tid = threadIdx.x;
    const int w = tid >> 5;
    const int lane = tid & 31;
    const int bh = blockIdx.y;
    const int qbase = blockIdx.x * 128;

    const int lr = lane >> 2;     // 0..7
    const int lk = lane & 3;      // 0..3
    const int rw = w * 16 + lr;   // A fragment base row

    convert_fill(g_Q + ((size_t)bh * Lx + qbase) * DHx, Qhi, Qlo, tid);

    float rm0 = -1e30f, rm1 = -1e30f;

    for (int t = 0; t < 16; t++) {
        __syncthreads();   // previous tile fully consumed (mma results in regs)
        convert_fill(g_K + ((size_t)bh * Lx + t * 128) * DHx, Khi, Klo, tid);
        __syncthreads();

        float C[16][4];
#pragma unroll
        for (int n = 0; n < 16; n++)
#pragma unroll
            for (int j = 0; j < 4; j++) C[n][j] = 0.f;

        for (int k8 = 0; k8 < 64; k8 += 8) {
            uint32_t ah[4], al[4];
            const int a0 = rw * SSTR + k8 + lk;
            const int a1 = (rw + 8) * SSTR + k8 + lk;
            ah[0] = __float_as_uint(Qhi[a0]);
            ah[1] = __float_as_uint(Qhi[a1]);
            ah[2] = __float_as_uint(Qhi[a0 + 4]);
            ah[3] = __float_as_uint(Qhi[a1 + 4]);
            al[0] = __float_as_uint(Qlo[a0]);
            al[1] = __float_as_uint(Qlo[a1]);
            al[2] = __float_as_uint(Qlo[a0 + 4]);
            al[3] = __float_as_uint(Qlo[a1 + 4]);
#pragma unroll
            for (int n = 0; n < 16; n++) {
                const int key = n * 8 + lr;
                const int b0 = key * SSTR + k8 + lk;
                uint32_t bhp[2], blp[2];
                bhp[0] = __float_as_uint(Khi[b0]);
                bhp[1] = __float_as_uint(Khi[b0 + 4]);
                blp[0] = __float_as_uint(Klo[b0]);
                blp[1] = __float_as_uint(Klo[b0 + 4]);
                mma_tf32(C[n], ah, bhp);   // hi*hi
                mma_tf32(C[n], ah, blp);   // hi*lo
                mma_tf32(C[n], al, bhp);   // lo*hi
            }
        }

#pragma unroll
        for (int n = 0; n < 16; n++) {
            rm0 = fmaxf(rm0, fmaxf(C[n][0], C[n][1]));
            rm1 = fmaxf(rm1, fmaxf(C[n][2], C[n][3]));
        }
    }

    // reduce across the 4 lanes sharing each C row (lane ^ 1, lane ^ 2)
    rm0 = fmaxf(rm0, __shfl_xor_sync(0xffffffffu, rm0, 1));
    rm0 = fmaxf(rm0, __shfl_xor_sync(0xffffffffu, rm0, 2));
    rm1 = fmaxf(rm1, __shfl_xor_sync(0xffffffffu, rm1, 1));
    rm1 = fmaxf(rm1, __shfl_xor_sync(0xffffffffu, rm1, 2));

    if (lk == 0) {
        g_rowmax[(size_t)bh * Lx + qbase + rw] = rm0;
        g_rowmax[(size_t)bh * Lx + qbase + rw + 8] = rm1;
    }
}

// ---------------------------------------------------------------------------
// K / V column sums (parallel over 16 row-chunks).
// ---------------------------------------------------------------------------
__global__ void zero_sums_kernel()
{
    int i = blockIdx.x * blockDim.x + threadIdx.x;
    if (i < BHx * DHx) { g_Ksum[i] = 0.f; g_Vsum[i] = 0.f; }
}

__global__ void partial_sums_kernel()
{
    const int bh = blockIdx.x;
    const int kb = blockIdx.y * 128;
    const int tid = threadIdx.x;
    const int d = tid & 63, s = tid >> 6;
    float ks = 0.f, vs = 0.f;
    for (int k = kb + s; k < kb + 128; k += 4) {
        ks += g_K[((size_t)bh * Lx + k) * DHx + d];
        vs += g_V[((size_t)bh * Lx + k) * DHx + d];
    }
    __shared__ float red[2][256];
    red[0][tid] = ks;
    red[1][tid] = vs;
    __syncthreads();
    if (tid < 64) {
        float a = red[0][d] + red[0][d + 64] + red[0][d + 128] + red[0][d + 192];
        float b = red[1][d] + red[1][d + 64] + red[1][d + 128] + red[1][d + 192];
        atomicAdd(&g_Ksum[bh * DHx + d], a);
        atomicAdd(&g_Vsum[bh * DHx + d], b);
    }
}

// ---------------------------------------------------------------------------
// M = SCALE * (rowmax - Q.Ksum / L), one thread per (bh, q), fp32 exact.
// ---------------------------------------------------------------------------
__global__ void mstat_kernel()
{
    int gidx = blockIdx.x * 256 + threadIdx.x;    // 0..65535
    int bh = gidx >> 11;
    const float* qp = g_Q + (size_t)gidx * DHx;
    const float* ks = g_Ksum + bh * DHx;
    float dot = 0.f;
#pragma unroll
    for (int d = 0; d < DHx; d += 4) {
        float4 a = *reinterpret_cast<const float4*>(qp + d);
        float4 b = *reinterpret_cast<const float4*>(ks + d);
        dot += a.x * b.x + a.y * b.y + a.z * b.z + a.w * b.w;
    }
    g_M[gidx] = SCALEF * (g_rowmax[gidx] - dot * (1.0f / Lx));
}

// ---------------------------------------------------------------------------
// Top-38 selection per bh (iterative max with lowest-index tiebreak)
// ---------------------------------------------------------------------------
__global__ void topk_kernel()
{
    int bh = blockIdx.x;
    int tid = threadIdx.x;
    __shared__ float vals[Lx];
    __shared__ float rv[256];
    __shared__ int ri[256];
    for (int i = tid; i < Lx; i += 256) vals[i] = g_M[(size_t)bh * Lx + i];
    __syncthreads();
    for (int it = 0; it < KTOP; it++) {
        float best = -1e30f;
        int bidx = 0;
        for (int i = tid; i < Lx; i += 256) {
            float v = vals[i];
            if (v > best) { best = v; bidx = i; }
        }
        rv[tid] = best;
        ri[tid] = bidx;
        __syncthreads();
        for (int s = 128; s > 0; s >>= 1) {
            if (tid < s) {
                if (rv[tid + s] > rv[tid] ||
                    (rv[tid + s] == rv[tid] && ri[tid + s] < ri[tid])) {
                    rv[tid] = rv[tid + s];
                    ri[tid] = ri[tid + s];
                }
            }
            __syncthreads();
        }
        if (tid == 0) {
            g_top[bh * KTOP + it] = ri[0];
            vals[ri[0]] = -1e30f;
        }
        __syncthreads();
    }
}

// ---------------------------------------------------------------------------
// Sparse attention, 2 queries per block.
// ---------------------------------------------------------------------------
__global__ __launch_bounds__(256)
void sparse_attn_kernel()
{
    const int bh = blockIdx.y;
    const int i0 = blockIdx.x;
    const int i1 = blockIdx.x + KHALF;
    const int tid = threadIdx.x;
    const int q0 = g_top[bh * KTOP + i0];
    const int q1 = g_top[bh * KTOP + i1];

    __shared__ float sc0[Lx];
    __shared__ float sc1[Lx];
    __shared__ float qrow[2][DHx];
    __shared__ float red[256];

    if (tid < 64) {
        qrow[0][tid] = g_Q[((size_t)bh * Lx + q0) * DHx + tid];
        qrow[1][tid] = g_Q[((size_t)bh * Lx + q1) * DHx + tid];
    }
    __syncthreads();

    const int warp = tid >> 5, lane = tid & 31;
    const float qa0 = qrow[0][lane], qa1 = qrow[0][lane + 32];
    const float qb0 = qrow[1][lane], qb1 = qrow[1][lane + 32];
    for (int k = warp; k < Lx; k += 8) {
        const float* kr = g_K + ((size_t)bh * Lx + k) * DHx;
        float k0 = kr[lane], k1 = kr[lane + 32];
        float pa = k0 * qa0 + k1 * qa1;
        float pb = k0 * qb0 + k1 * qb1;
#pragma unroll
        for (int o = 16; o > 0; o >>= 1) {
            pa += __shfl_xor_sync(0xffffffffu, pa, o);
            pb += __shfl_xor_sync(0xffffffffu, pb, o);
        }
        if (lane == 0) { sc0[k] = pa * SCALEF; sc1[k] = pb * SCALEF; }
    }
    __syncthreads();

    float inv0, inv1;
    for (int qq = 0; qq < 2; qq++) {
        float* sc = qq ? sc1 : sc0;
        float mx = -1e30f;
        for (int k = tid; k < Lx; k += 256) mx = fmaxf(mx, sc[k]);
        red[tid] = mx;
        __syncthreads();
        for (int s = 128; s > 0; s >>= 1) {
            if (tid < s) red[tid] = fmaxf(red[tid], red[tid + s]);
            __syncthreads();
        }
        mx = red[0];
        __syncthreads();
        float sum = 0.f;
        for (int k = tid; k < Lx; k += 256) {
            float e = __expf(sc[k] - mx);
            sc[k] = e;
            sum += e;
        }
        red[tid] = sum;
        __syncthreads();
        for (int s = 128; s > 0; s >>= 1) {
            if (tid < s) red[tid] += red[tid + s];
            __syncthreads();
        }
        if (qq == 0) inv0 = 1.0f / red[0]; else inv1 = 1.0f / red[0];
        __syncthreads();
    }

    const int d = tid & 63, s4 = tid >> 6;
    float acc0 = 0.f, acc1 = 0.f;
    for (int k = s4; k < Lx; k += 4) {
        float v = g_V[((size_t)bh * Lx + k) * DHx + d];
        acc0 += sc0[k] * v;
        acc1 += sc1[k] * v;
    }
    __shared__ float red2[2][256];
    red2[0][tid] = acc0;
    red2[1][tid] = acc1;
    __syncthreads();
    if (tid < 64) {
        float vm = g_Vsum[bh * DHx + d] * (1.0f / Lx);
        float c0 = (red2[0][d] + red2[0][d + 64] + red2[0][d + 128] + red2[0][d + 192]) * inv0;
        float c1 = (red2[1][d] + red2[1][d + 64] + red2[1][d + 128] + red2[1][d + 192]) * inv1;
        g_delta[((size_t)bh * KTOP + i0) * DHx + d] = c0 - vm;
        g_delta[((size_t)bh * KTOP + i1) * DHx + d] = c1 - vm;
    }
}

// ---------------------------------------------------------------------------
__global__ void base_kernel(const float* __restrict__ Wo, const float* __restrict__ bo)
{
    int b = blockIdx.x, j = threadIdx.x;
    float acc = bo[j];
    for (int c = 0; c < Dx; c++) {
        int h = c >> 6, d = c & 63;
        acc += g_Vsum[(b * Hx + h) * DHx + d] * (1.0f / Lx) * Wo[(size_t)c * Dx + j];
    }
    g_base[b * Dx + j] = acc;
}

__global__ void fill_kernel(float* __restrict__ out)
{
    size_t idx = (size_t)blockIdx.x * blockDim.x + threadIdx.x;
    if (idx < (size_t)Bx * Lx * Dx) {
        int b = (int)(idx / ((size_t)Lx * Dx));
        int j = (int)(idx % Dx);
        out[idx] = g_base[b * Dx + j];
    }
}

__global__ void scatter_kernel(const float* __restrict__ Wo, float* __restrict__ out)
{
    const int bh = blockIdx.y;
    const int i = blockIdx.x;
    const int j = threadIdx.x;  // 512
    const int b = bh >> 3, h = bh & 7;
    const int l = g_top[bh * KTOP + i];
    __shared__ float dl[DHx];
    if (j < 64) dl[j] = g_delta[((size_t)bh * KTOP + i) * DHx + j];
    __syncthreads();
    float acc = 0.f;
#pragma unroll 16
    for (int d = 0; d < 64; d++) acc += dl[d] * Wo[(size_t)(h * 64 + d) * Dx + j];
    atomicAdd(&out[((size_t)b * Lx + l) * Dx + j], acc);
}

// ---------------------------------------------------------------------------
extern "C" void kernel_launch(void* const* d_in, const int* in_sizes, int n_in,
                              void* d_out, int out_size)
{
    const float* x  = (const float*)d_in[0];
    const float* Wq = (const float*)d_in[1];
    const float* bq = (const float*)d_in[2];
    const float* Wk = (const float*)d_in[3];
    const float* bk = (const float*)d_in[4];
    const float* Wv = (const float*)d_in[5];
    const float* bv = (const float*)d_in[6];
    const float* Wo = (const float*)d_in[7];
    const float* bo = (const float*)d_in[8];
    float* out = (float*)d_out;

    (void)in_sizes; (void)n_in; (void)out_size;

    const int score_smem = 4 * 128 * SSTR * (int)sizeof(float);  // 139264
    cudaFuncSetAttribute(score_mma_kernel,
                         cudaFuncAttributeMaxDynamicSharedMemorySize, score_smem);

    float* gQ; cudaGetSymbolAddress((void**)&gQ, g_Q);
    float* gK; cudaGetSymbolAddress((void**)&gK, g_K);
    float* gV; cudaGetSymbolAddress((void**)&gV, g_V);

    dim3 pg(Dx / 128, (Bx * Lx) / 128);  // (4, 64)
    proj_kernel<<<pg, 256>>>(x, Wq, bq, gQ);
    proj_kernel<<<pg, 256>>>(x, Wk, bk, gK);
    proj_kernel<<<pg, 256>>>(x, Wv, bv, gV);

    // launch index 3 -> ncu capture target
    score_mma_kernel<<<dim3(Lx / 128, BHx), 256, score_smem>>>();

    zero_sums_kernel<<<(BHx * DHx + 255) / 256, 256>>>();
    partial_sums_kernel<<<dim3(BHx, 16), 256>>>();
    mstat_kernel<<<BHx * Lx / 256, 256>>>();

    topk_kernel<<<BHx, 256>>>();

    sparse_attn_kernel<<<dim3(KHALF, BHx), 256>>>();

    base_kernel<<<Bx, Dx>>>(Wo, bo);
    fill_kernel<<<(Bx * Lx * Dx + 255) / 256, 256>>>(out);
    scatter_kernel<<<dim3(KTOP, BHx), Dx>>>(Wo, out);
}

// round 9
// speedup vs baseline: 1.6546x; 1.3795x over previous
#include <cuda_runtime.h>
#include <cuda_fp16.h>
#include <math.h>
#include <stdint.h>

#define Bx 4
#define Lx 2048
#define Dx 512
#define Hx 8
#define DHx 64
#define BHx 32
#define KTOP 38
#define KHALF 19
#define SCALEF 0.125f
#define SH 72   // halves per smem row (stride)
#define SW 36   // 32-bit words per smem row; 36 % 32 == 4 -> conflict-free frags

// ---------------- scratch (device globals; no allocation allowed) ----------
__device__ float  g_Q[BHx * Lx * DHx];
__device__ float  g_K[BHx * Lx * DHx];
__device__ float  g_V[BHx * Lx * DHx];
__device__ __half g_Xhi[Bx * Lx * Dx];
__device__ __half g_Xlo[Bx * Lx * Dx];
__device__ __half g_WThi[3 * Dx * Dx];   // W^T, [c][k], per projection
__device__ __half g_WTlo[3 * Dx * Dx];
__device__ __half g_Qhi[BHx * Lx * DHx];
__device__ __half g_Qlo[BHx * Lx * DHx];
__device__ __half g_Khi[BHx * Lx * DHx];
__device__ __half g_Klo[BHx * Lx * DHx];
__device__ float  g_rowmax[BHx * Lx];
__device__ float  g_M[BHx * Lx];
__device__ int    g_top[BHx * KTOP];
__device__ float  g_Ksum[BHx * DHx];
__device__ float  g_Vsum[BHx * DHx];
__device__ float  g_delta[BHx * KTOP * DHx];
__device__ float  g_base[Bx * Dx];

// ---------------- f16 mma helper (sm_80+ PTX; legal on plain sm_103) -------
__device__ __forceinline__ void mma_f16(float c[4], const uint32_t a[4],
                                        uint32_t b0, uint32_t b1) {
    asm volatile(
        "mma.sync.aligned.m16n8k16.row.col.f32.f16.f16.f32 "
        "{%0,%1,%2,%3}, {%4,%5,%6,%7}, {%8,%9}, {%0,%1,%2,%3};"
        : "+f"(c[0]), "+f"(c[1]), "+f"(c[2]), "+f"(c[3])
        : "r"(a[0]), "r"(a[1]), "r"(a[2]), "r"(a[3]), "r"(b0), "r"(b1));
}

__device__ __forceinline__ void split_h(float f, __half& h, __half& l) {
    h = __float2half_rn(f);
    l = __float2half_rn(f - __half2float(h));
}

// ---------------------------------------------------------------------------
// prep_w: transpose W[k][c] -> WT[c][k] and split to fp16 hi/lo. grid(16,16,3).
// ---------------------------------------------------------------------------
__global__ void prep_w_kernel(const float* __restrict__ Wq,
                              const float* __restrict__ Wk,
                              const float* __restrict__ Wv)
{
    __shared__ float s[32][33];
    const float* W = (blockIdx.z == 0) ? Wq : (blockIdx.z == 1) ? Wk : Wv;
    __half* dh = g_WThi + (size_t)blockIdx.z * Dx * Dx;
    __half* dl = g_WTlo + (size_t)blockIdx.z * Dx * Dx;
    const int kt = blockIdx.y * 32, ct = blockIdx.x * 32;
    const int tid = threadIdx.x;
    {
        int r = tid >> 3, c4 = (tid & 7) * 4;
        float4 v = *reinterpret_cast<const float4*>(&W[(size_t)(kt + r) * Dx + ct + c4]);
        s[r][c4] = v.x; s[r][c4 + 1] = v.y; s[r][c4 + 2] = v.z; s[r][c4 + 3] = v.w;
    }
    __syncthreads();
    {
        int cw = tid >> 3, k4 = (tid & 7) * 4;
        size_t o = (size_t)(ct + cw) * Dx + kt + k4;
#pragma unroll
        for (int j = 0; j < 4; j += 2) {
            __half h0, l0, h1, l1;
            split_h(s[k4 + j][cw], h0, l0);
            split_h(s[k4 + j + 1][cw], h1, l1);
            *reinterpret_cast<__half2*>(&dh[o + j]) = __halves2half2(h0, h1);
            *reinterpret_cast<__half2*>(&dl[o + j]) = __halves2half2(l0, l1);
        }
    }
}

// ---------------------------------------------------------------------------
// prep_x: split x to fp16 hi/lo. grid 4096 x 256, one float4 per thread.
// ---------------------------------------------------------------------------
__global__ void prep_x_kernel(const float* __restrict__ X)
{
    size_t i4 = (size_t)blockIdx.x * 256 + threadIdx.x;
    float4 v = *reinterpret_cast<const float4*>(X + i4 * 4);
    __half h0, l0, h1, l1, h2, l2, h3, l3;
    split_h(v.x, h0, l0); split_h(v.y, h1, l1);
    split_h(v.z, h2, l2); split_h(v.w, h3, l3);
    size_t o = i4 * 4;
    *reinterpret_cast<__half2*>(&g_Xhi[o])     = __halves2half2(h0, h1);
    *reinterpret_cast<__half2*>(&g_Xhi[o + 2]) = __halves2half2(h2, h3);
    *reinterpret_cast<__half2*>(&g_Xlo[o])     = __halves2half2(l0, l1);
    *reinterpret_cast<__half2*>(&g_Xlo[o + 2]) = __halves2half2(l2, l3);
}

// ---------------------------------------------------------------------------
// proj_mma: Y = X @ W + b via m16n8k16 f16 hi/lo split (3 mma).
// Tile 128m x 128n, BK=32. Writes fp32 out and (optionally) fp16 hi/lo out.
// Warp (wm = w>>2 in {0,1}, wn = w&3 in {0..3}) owns 4 m-tiles x 4 n-tiles.
// ---------------------------------------------------------------------------
#define PROJ_SMEM (4 * 128 * SH * 2)

__global__ __launch_bounds__(256)
void proj_mma_kernel(const __half* __restrict__ Xhi, const __half* __restrict__ Xlo,
                     const __half* __restrict__ WThi, const __half* __restrict__ WTlo,
                     const float* __restrict__ bias, float* __restrict__ out,
                     __half* __restrict__ outHi, __half* __restrict__ outLo)
{
    extern __shared__ __half smh[];
    __half* Xh = smh;
    __half* Xl = Xh + 128 * SH;
    __half* Wh = Xl + 128 * SH;
    __half* Wl = Wh + 128 * SH;

    const int tid = threadIdx.x;
    const int w = tid >> 5, lane = tid & 31;
    const int gr = lane >> 2, tc = lane & 3;
    const int wm = w >> 2, wn = w & 3;
    const int mbase = blockIdx.y * 128;
    const int nbase = blockIdx.x * 128;

    float C[16][4];
#pragma unroll
    for (int p = 0; p < 16; p++)
#pragma unroll
        for (int j = 0; j < 4; j++) C[p][j] = 0.f;

    for (int kt = 0; kt < Dx; kt += 32) {
        __syncthreads();
#pragma unroll
        for (int i = 0; i < 2; i++) {
            int idx = tid + i * 256;          // 0..511
            int r = idx >> 2;
            int u = (idx & 3) * 8;
            size_t xs = (size_t)(mbase + r) * Dx + kt + u;
            *reinterpret_cast<uint4*>(Xh + r * SH + u) =
                *reinterpret_cast<const uint4*>(Xhi + xs);
            *reinterpret_cast<uint4*>(Xl + r * SH + u) =
                *reinterpret_cast<const uint4*>(Xlo + xs);
            size_t ws = (size_t)(nbase + r) * Dx + kt + u;
            *reinterpret_cast<uint4*>(Wh + r * SH + u) =
                *reinterpret_cast<const uint4*>(WThi + ws);
            *reinterpret_cast<uint4*>(Wl + r * SH + u) =
                *reinterpret_cast<const uint4*>(WTlo + ws);
        }
        __syncthreads();

#pragma unroll
        for (int k16 = 0; k16 < 2; k16++) {
            const int kw = k16 * 8;
            uint32_t ah[4][4], al[4][4];
#pragma unroll
            for (int mi = 0; mi < 4; mi++) {
                int row = (wm * 4 + mi) * 16 + gr;
                const uint32_t* p0h = reinterpret_cast<const uint32_t*>(Xh) + row * SW + kw;
                const uint32_t* p0l = reinterpret_cast<const uint32_t*>(Xl) + row * SW + kw;
                ah[mi][0] = p0h[tc];            ah[mi][1] = p0h[8 * SW + tc];
                ah[mi][2] = p0h[tc + 4];        ah[mi][3] = p0h[8 * SW + tc + 4];
                al[mi][0] = p0l[tc];            al[mi][1] = p0l[8 * SW + tc];
                al[mi][2] = p0l[tc + 4];        al[mi][3] = p0l[8 * SW + tc + 4];
            }
#pragma unroll
            for (int ni = 0; ni < 4; ni++) {
                int key = (wn * 4 + ni) * 8 + gr;
                const uint32_t* qh = reinterpret_cast<const uint32_t*>(Wh) + key * SW + kw;
                const uint32_t* ql = reinterpret_cast<const uint32_t*>(Wl) + key * SW + kw;
                uint32_t bh0 = qh[tc], bh1 = qh[tc + 4];
                uint32_t bl0 = ql[tc], bl1 = ql[tc + 4];
#pragma unroll
                for (int mi = 0; mi < 4; mi++) {
                    mma_f16(C[mi * 4 + ni], ah[mi], bh0, bh1);
                    mma_f16(C[mi * 4 + ni], ah[mi], bl0, bl1);
                    mma_f16(C[mi * 4 + ni], al[mi], bh0, bh1);
                }
            }
        }
    }

    // epilogue: [bh][l][d] layout, fp32 + optional fp16 hi/lo
#pragma unroll
    for (int mi = 0; mi < 4; mi++) {
#pragma unroll
        for (int ni = 0; ni < 4; ni++) {
            const float* c = C[mi * 4 + ni];
            int col = nbase + (wn * 4 + ni) * 8 + 2 * tc;
            int h = col >> 6, d = col & 63;
            float b0 = bias[col], b1 = bias[col + 1];
#pragma unroll
            for (int half_ = 0; half_ < 2; half_++) {
                int r = mbase + (wm * 4 + mi) * 16 + gr + half_ * 8;
                int bb = r >> 11, l = r & 2047;
                size_t o = (((size_t)(bb * Hx + h)) * Lx + l) * DHx + d;
                float v0 = c[half_ * 2] + b0;
                float v1 = c[half_ * 2 + 1] + b1;
                *reinterpret_cast<float2*>(&out[o]) = make_float2(v0, v1);
                if (outHi) {
                    __half h0, l0, h1, l1;
                    split_h(v0, h0, l0);
                    split_h(v1, h1, l1);
                    *reinterpret_cast<__half2*>(&outHi[o]) = __halves2half2(h0, h1);
                    *reinterpret_cast<__half2*>(&outLo[o]) = __halves2half2(l0, l1);
                }
            }
        }
    }
}

// ---------------------------------------------------------------------------
// score_mma: rowmax(Q_tile[128,64] @ K^T) via m16n8k16 f16 hi/lo split.
// Tiles are pre-split halves -> smem fill is pure uint4 copy.
// ---------------------------------------------------------------------------
#define SCORE_SMEM (4 * 128 * SH * 2 + 4 * 128 * 4)

__global__ __launch_bounds__(256)
void score_mma_kernel()
{
    extern __shared__ __half smh[];
    __half* Qh = smh;
    __half* Ql = Qh + 128 * SH;
    __half* Kh = Ql + 128 * SH;
    __half* Kl = Kh + 128 * SH;
    float* red = reinterpret_cast<float*>(Kl + 128 * SH);   // [4][128]

    const int tid = threadIdx.x;
    const int w = tid >> 5, lane = tid & 31;
    const int gr = lane >> 2, tc = lane & 3;
    const int wm = w >> 2, wn = w & 3;
    const int bh = blockIdx.y;
    const int qbase = blockIdx.x * 128;

    // Q fill once: 128 rows x 64 halves per buffer
#pragma unroll
    for (int i = 0; i < 4; i++) {
        int idx = tid + i * 256;        // 0..1023
        int r = idx >> 3;
        int u = (idx & 7) * 8;
        size_t qs = ((size_t)bh * Lx + qbase + r) * DHx + u;
        *reinterpret_cast<uint4*>(Qh + r * SH + u) =
            *reinterpret_cast<const uint4*>(g_Qhi + qs);
        *reinterpret_cast<uint4*>(Ql + r * SH + u) =
            *reinterpret_cast<const uint4*>(g_Qlo + qs);
    }

    float rm0[4], rm1[4];
#pragma unroll
    for (int mi = 0; mi < 4; mi++) { rm0[mi] = -1e30f; rm1[mi] = -1e30f; }

    for (int t = 0; t < 16; t++) {
        __syncthreads();
#pragma unroll
        for (int i = 0; i < 4; i++) {
            int idx = tid + i * 256;
            int r = idx >> 3;
            int u = (idx & 7) * 8;
            size_t ks = ((size_t)bh * Lx + t * 128 + r) * DHx + u;
            *reinterpret_cast<uint4*>(Kh + r * SH + u) =
                *reinterpret_cast<const uint4*>(g_Khi + ks);
            *reinterpret_cast<uint4*>(Kl + r * SH + u) =
                *reinterpret_cast<const uint4*>(g_Klo + ks);
        }
        __syncthreads();

        float C[16][4];
#pragma unroll
        for (int p = 0; p < 16; p++)
#pragma unroll
            for (int j = 0; j < 4; j++) C[p][j] = 0.f;

#pragma unroll
        for (int k16 = 0; k16 < 4; k16++) {
            const int kw = k16 * 8;
            uint32_t ah[4][4], al[4][4];
#pragma unroll
            for (int mi = 0; mi < 4; mi++) {
                int row = (wm * 4 + mi) * 16 + gr;
                const uint32_t* p0h = reinterpret_cast<const uint32_t*>(Qh) + row * SW + kw;
                const uint32_t* p0l = reinterpret_cast<const uint32_t*>(Ql) + row * SW + kw;
                ah[mi][0] = p0h[tc];            ah[mi][1] = p0h[8 * SW + tc];
                ah[mi][2] = p0h[tc + 4];        ah[mi][3] = p0h[8 * SW + tc + 4];
                al[mi][0] = p0l[tc];            al[mi][1] = p0l[8 * SW + tc];
                al[mi][2] = p0l[tc + 4];        al[mi][3] = p0l[8 * SW + tc + 4];
            }
#pragma unroll
            for (int ni = 0; ni < 4; ni++) {
                int key = (wn * 4 + ni) * 8 + gr;
                const uint32_t* qh = reinterpret_cast<const uint32_t*>(Kh) + key * SW + kw;
                const uint32_t* ql = reinterpret_cast<const uint32_t*>(Kl) + key * SW + kw;
                uint32_t bh0 = qh[tc], bh1 = qh[tc + 4];
                uint32_t bl0 = ql[tc], bl1 = ql[tc + 4];
#pragma unroll
                for (int mi = 0; mi < 4; mi++) {
                    mma_f16(C[mi * 4 + ni], ah[mi], bh0, bh1);
                    mma_f16(C[mi * 4 + ni], ah[mi], bl0, bl1);
                    mma_f16(C[mi * 4 + ni], al[mi], bh0, bh1);
                }
            }
        }

#pragma unroll
        for (int mi = 0; mi < 4; mi++)
#pragma unroll
            for (int ni = 0; ni < 4; ni++) {
                const float* c = C[mi * 4 + ni];
                rm0[mi] = fmaxf(rm0[mi], fmaxf(c[0], c[1]));
                rm1[mi] = fmaxf(rm1[mi], fmaxf(c[2], c[3]));
            }
    }

    // reduce over tc (quad lanes share gr)
#pragma unroll
    for (int mi = 0; mi < 4; mi++) {
        rm0[mi] = fmaxf(rm0[mi], __shfl_xor_sync(0xffffffffu, rm0[mi], 1));
        rm0[mi] = fmaxf(rm0[mi], __shfl_xor_sync(0xffffffffu, rm0[mi], 2));
        rm1[mi] = fmaxf(rm1[mi], __shfl_xor_sync(0xffffffffu, rm1[mi], 1));
        rm1[mi] = fmaxf(rm1[mi], __shfl_xor_sync(0xffffffffu, rm1[mi], 2));
    }
    if (tc == 0) {
#pragma unroll
        for (int mi = 0; mi < 4; mi++) {
            int row = (wm * 4 + mi) * 16 + gr;
            red[wn * 128 + row] = rm0[mi];
            red[wn * 128 + row + 8] = rm1[mi];
        }
    }
    __syncthreads();
    if (tid < 128) {
        float m = fmaxf(fmaxf(red[tid], red[128 + tid]),
                        fmaxf(red[256 + tid], red[384 + tid]));
        g_rowmax[(size_t)bh * Lx + qbase + tid] = m;
    }
}

// ---------------------------------------------------------------------------
// K / V column sums (parallel over 16 row-chunks).
// ---------------------------------------------------------------------------
__global__ void zero_sums_kernel()
{
    int i = blockIdx.x * blockDim.x + threadIdx.x;
    if (i < BHx * DHx) { g_Ksum[i] = 0.f; g_Vsum[i] = 0.f; }
}

__global__ void partial_sums_kernel()
{
    const int bh = blockIdx.x;
    const int kb = blockIdx.y * 128;
    const int tid = threadIdx.x;
    const int d = tid & 63, s = tid >> 6;
    float ks = 0.f, vs = 0.f;
    for (int k = kb + s; k < kb + 128; k += 4) {
        ks += g_K[((size_t)bh * Lx + k) * DHx + d];
        vs += g_V[((size_t)bh * Lx + k) * DHx + d];
    }
    __shared__ float red[2][256];
    red[0][tid] = ks;
    red[1][tid] = vs;
    __syncthreads();
    if (tid < 64) {
        float a = red[0][d] + red[0][d + 64] + red[0][d + 128] + red[0][d + 192];
        float b = red[1][d] + red[1][d + 64] + red[1][d + 128] + red[1][d + 192];
        atomicAdd(&g_Ksum[bh * DHx + d], a);
        atomicAdd(&g_Vsum[bh * DHx + d], b);
    }
}

// ---------------------------------------------------------------------------
// M = SCALE * (rowmax - Q.Ksum / L)
// ---------------------------------------------------------------------------
__global__ void mstat_kernel()
{
    int gidx = blockIdx.x * 256 + threadIdx.x;
    int bh = gidx >> 11;
    const float* qp = g_Q + (size_t)gidx * DHx;
    const float* ks = g_Ksum + bh * DHx;
    float dot = 0.f;
#pragma unroll
    for (int d = 0; d < DHx; d += 4) {
        float4 a = *reinterpret_cast<const float4*>(qp + d);
        float4 b = *reinterpret_cast<const float4*>(ks + d);
        dot += a.x * b.x + a.y * b.y + a.z * b.z + a.w * b.w;
    }
    g_M[gidx] = SCALEF * (g_rowmax[gidx] - dot * (1.0f / Lx));
}

// ---------------------------------------------------------------------------
// Top-38 selection per bh (iterative max with lowest-index tiebreak)
// ---------------------------------------------------------------------------
__global__ void topk_kernel()
{
    int bh = blockIdx.x;
    int tid = threadIdx.x;
    __shared__ float vals[Lx];
    __shared__ float rv[256];
    __shared__ int ri[256];
    for (int i = tid; i < Lx; i += 256) vals[i] = g_M[(size_t)bh * Lx + i];
    __syncthreads();
    for (int it = 0; it < KTOP; it++) {
        float best = -1e30f;
        int bidx = 0;
        for (int i = tid; i < Lx; i += 256) {
            float v = vals[i];
            if (v > best) { best = v; bidx = i; }
        }
        rv[tid] = best;
        ri[tid] = bidx;
        __syncthreads();
        for (int s = 128; s > 0; s >>= 1) {
            if (tid < s) {
                if (rv[tid + s] > rv[tid] ||
                    (rv[tid + s] == rv[tid] && ri[tid + s] < ri[tid])) {
                    rv[tid] = rv[tid + s];
                    ri[tid] = ri[tid + s];
                }
            }
            __syncthreads();
        }
        if (tid == 0) {
            g_top[bh * KTOP + it] = ri[0];
            vals[ri[0]] = -1e30f;
        }
        __syncthreads();
    }
}

// ---------------------------------------------------------------------------
// Sparse attention, 2 queries per block (exact fp32).
// ---------------------------------------------------------------------------
__global__ __launch_bounds__(256)
void sparse_attn_kernel()
{
    const int bh = blockIdx.y;
    const int i0 = blockIdx.x;
    const int i1 = blockIdx.x + KHALF;
    const int tid = threadIdx.x;
    const int q0 = g_top[bh * KTOP + i0];
    const int q1 = g_top[bh * KTOP + i1];

    __shared__ float sc0[Lx];
    __shared__ float sc1[Lx];
    __shared__ float qrow[2][DHx];
    __shared__ float red[256];

    if (tid < 64) {
        qrow[0][tid] = g_Q[((size_t)bh * Lx + q0) * DHx + tid];
        qrow[1][tid] = g_Q[((size_t)bh * Lx + q1) * DHx + tid];
    }
    __syncthreads();

    const int warp = tid >> 5, lane = tid & 31;
    const float qa0 = qrow[0][lane], qa1 = qrow[0][lane + 32];
    const float qb0 = qrow[1][lane], qb1 = qrow[1][lane + 32];
    for (int k = warp; k < Lx; k += 8) {
        const float* kr = g_K + ((size_t)bh * Lx + k) * DHx;
        float k0 = kr[lane], k1 = kr[lane + 32];
        float pa = k0 * qa0 + k1 * qa1;
        float pb = k0 * qb0 + k1 * qb1;
#pragma unroll
        for (int o = 16; o > 0; o >>= 1) {
            pa += __shfl_xor_sync(0xffffffffu, pa, o);
            pb += __shfl_xor_sync(0xffffffffu, pb, o);
        }
        if (lane == 0) { sc0[k] = pa * SCALEF; sc1[k] = pb * SCALEF; }
    }
    __syncthreads();

    float inv0, inv1;
    for (int qq = 0; qq < 2; qq++) {
        float* sc = qq ? sc1 : sc0;
        float mx = -1e30f;
        for (int k = tid; k < Lx; k += 256) mx = fmaxf(mx, sc[k]);
        red[tid] = mx;
        __syncthreads();
        for (int s = 128; s > 0; s >>= 1) {
            if (tid < s) red[tid] = fmaxf(red[tid], red[tid + s]);
            __syncthreads();
        }
        mx = red[0];
        __syncthreads();
        float sum = 0.f;
        for (int k = tid; k < Lx; k += 256) {
            float e = __expf(sc[k] - mx);
            sc[k] = e;
            sum += e;
        }
        red[tid] = sum;
        __syncthreads();
        for (int s = 128; s > 0; s >>= 1) {
            if (tid < s) red[tid] += red[tid + s];
            __syncthreads();
        }
        if (qq == 0) inv0 = 1.0f / red[0]; else inv1 = 1.0f / red[0];
        __syncthreads();
    }

    const int d = tid & 63, s4 = tid >> 6;
    float acc0 = 0.f, acc1 = 0.f;
    for (int k = s4; k < Lx; k += 4) {
        float v = g_V[((size_t)bh * Lx + k) * DHx + d];
        acc0 += sc0[k] * v;
        acc1 += sc1[k] * v;
    }
    __shared__ float red2[2][256];
    red2[0][tid] = acc0;
    red2[1][tid] = acc1;
    __syncthreads();
    if (tid < 64) {
        float vm = g_Vsum[bh * DHx + d] * (1.0f / Lx);
        float c0 = (red2[0][d] + red2[0][d + 64] + red2[0][d + 128] + red2[0][d + 192]) * inv0;
        float c1 = (red2[1][d] + red2[1][d + 64] + red2[1][d + 128] + red2[1][d + 192]) * inv1;
        g_delta[((size_t)bh * KTOP + i0) * DHx + d] = c0 - vm;
        g_delta[((size_t)bh * KTOP + i1) * DHx + d] = c1 - vm;
    }
}

// ---------------------------------------------------------------------------
__global__ void base_kernel(const float* __restrict__ Wo, const float* __restrict__ bo)
{
    int b = blockIdx.x, j = threadIdx.x;
    float acc = bo[j];
    for (int c = 0; c < Dx; c++) {
        int h = c >> 6, d = c & 63;
        acc += g_Vsum[(b * Hx + h) * DHx + d] * (1.0f / Lx) * Wo[(size_t)c * Dx + j];
    }
    g_base[b * Dx + j] = acc;
}

__global__ void fill_kernel(float* __restrict__ out)
{
    size_t idx = (size_t)blockIdx.x * blockDim.x + threadIdx.x;
    if (idx < (size_t)Bx * Lx * Dx) {
        int b = (int)(idx / ((size_t)Lx * Dx));
        int j = (int)(idx % Dx);
        out[idx] = g_base[b * Dx + j];
    }
}

__global__ void scatter_kernel(const float* __restrict__ Wo, float* __restrict__ out)
{
    const int bh = blockIdx.y;
    const int i = blockIdx.x;
    const int j = threadIdx.x;  // 512
    const int b = bh >> 3, h = bh & 7;
    const int l = g_top[bh * KTOP + i];
    __shared__ float dl[DHx];
    if (j < 64) dl[j] = g_delta[((size_t)bh * KTOP + i) * DHx + j];
    __syncthreads();
    float acc = 0.f;
#pragma unroll 16
    for (int d = 0; d < 64; d++) acc += dl[d] * Wo[(size_t)(h * 64 + d) * Dx + j];
    atomicAdd(&out[((size_t)b * Lx + l) * Dx + j], acc);
}

// ---------------------------------------------------------------------------
extern "C" void kernel_launch(void* const* d_in, const int* in_sizes, int n_in,
                              void* d_out, int out_size)
{
    const float* x  = (const float*)d_in[0];
    const float* Wq = (const float*)d_in[1];
    const float* bq = (const float*)d_in[2];
    const float* Wk = (const float*)d_in[3];
    const float* bk = (const float*)d_in[4];
    const float* Wv = (const float*)d_in[5];
    const float* bv = (const float*)d_in[6];
    const float* Wo = (const float*)d_in[7];
    const float* bo = (const float*)d_in[8];
    float* out = (float*)d_out;

    (void)in_sizes; (void)n_in; (void)out_size;

    cudaFuncSetAttribute(proj_mma_kernel,
                         cudaFuncAttributeMaxDynamicSharedMemorySize, PROJ_SMEM);
    cudaFuncSetAttribute(score_mma_kernel,
                         cudaFuncAttributeMaxDynamicSharedMemorySize, SCORE_SMEM);

    float*  gQ;   cudaGetSymbolAddress((void**)&gQ,   g_Q);
    float*  gK;   cudaGetSymbolAddress((void**)&gK,   g_K);
    float*  gV;   cudaGetSymbolAddress((void**)&gV,   g_V);
    __half* xhi;  cudaGetSymbolAddress((void**)&xhi,  g_Xhi);
    __half* xlo;  cudaGetSymbolAddress((void**)&xlo,  g_Xlo);
    __half* wthi; cudaGetSymbolAddress((void**)&wthi, g_WThi);
    __half* wtlo; cudaGetSymbolAddress((void**)&wtlo, g_WTlo);
    __half* qhi;  cudaGetSymbolAddress((void**)&qhi,  g_Qhi);
    __half* qlo;  cudaGetSymbolAddress((void**)&qlo,  g_Qlo);
    __half* khi;  cudaGetSymbolAddress((void**)&khi,  g_Khi);
    __half* klo;  cudaGetSymbolAddress((void**)&klo,  g_Klo);

    prep_w_kernel<<<dim3(16, 16, 3), 256>>>(Wq, Wk, Wv);
    prep_x_kernel<<<(Bx * Lx * Dx / 4) / 256, 256>>>(x);

    dim3 pg(Dx / 128, (Bx * Lx) / 128);  // (4, 64)
    proj_mma_kernel<<<pg, 256, PROJ_SMEM>>>(xhi, xlo, wthi, wtlo, bq, gQ, qhi, qlo);
    proj_mma_kernel<<<pg, 256, PROJ_SMEM>>>(xhi, xlo, wthi + Dx * Dx, wtlo + Dx * Dx,
                                            bk, gK, khi, klo);
    proj_mma_kernel<<<pg, 256, PROJ_SMEM>>>(xhi, xlo, wthi + 2 * Dx * Dx, wtlo + 2 * Dx * Dx,
                                            bv, gV, (half*)nullptr, (half*)nullptr);

    // launch index 5 -> ncu capture target (-s 5 -c 1)
    score_mma_kernel<<<dim3(Lx / 128, BHx), 256, SCORE_SMEM>>>();

    zero_sums_kernel<<<(BHx * DHx + 255) / 256, 256>>>();
    partial_sums_kernel<<<dim3(BHx, 16), 256>>>();
    mstat_kernel<<<BHx * Lx / 256, 256>>>();

    topk_kernel<<<BHx, 256>>>();

    sparse_attn_kernel<<<dim3(KHALF, BHx), 256>>>();

    base_kernel<<<Bx, Dx>>>(Wo, bo);
    fill_kernel<<<(Bx * Lx * Dx + 255) / 256, 256>>>(out);
    scatter_kernel<<<dim3(KTOP, BHx), Dx>>>(Wo, out);
}

// round 10
// speedup vs baseline: 1.6682x; 1.0082x over previous
#include <cuda_runtime.h>
#include <cuda_fp16.h>
#include <math.h>
#include <stdint.h>

#define Bx 4
#define Lx 2048
#define Dx 512
#define Hx 8
#define DHx 64
#define BHx 32
#define KTOP 38
#define KHALF 19
#define SCALEF 0.125f
#define SH 72   // score smem halves per row
#define SW 36   // score smem words per row (36 % 32 == 4 -> conflict-free)
#define PSH 40  // proj stage halves per row (32 data + 8 pad)
#define PSW 20  // proj stage words per row (20*gr+tc covers all banks)

// ---------------- scratch (device globals; no allocation allowed) ----------
__device__ float  g_Q[BHx * Lx * DHx];
__device__ float  g_K[BHx * Lx * DHx];
__device__ float  g_V[BHx * Lx * DHx];
__device__ __half g_Xhi[Bx * Lx * Dx];
__device__ __half g_Xlo[Bx * Lx * Dx];
__device__ __half g_WThi[3 * Dx * Dx];   // W^T, [c][k], per projection
__device__ __half g_WTlo[3 * Dx * Dx];
__device__ __half g_Qhi[BHx * Lx * DHx];
__device__ __half g_Qlo[BHx * Lx * DHx];
__device__ __half g_Khi[BHx * Lx * DHx];
__device__ __half g_Klo[BHx * Lx * DHx];
__device__ float  g_rowmax[BHx * Lx];
__device__ float  g_M[BHx * Lx];
__device__ int    g_top[BHx * KTOP];
__device__ float  g_Ksum[BHx * DHx];
__device__ float  g_Vsum[BHx * DHx];
__device__ float  g_delta[BHx * KTOP * DHx];
__device__ float  g_base[Bx * Dx];

// ---------------- helpers ----------------------------------------------------
__device__ __forceinline__ void mma_f16(float c[4], const uint32_t a[4],
                                        uint32_t b0, uint32_t b1) {
    asm volatile(
        "mma.sync.aligned.m16n8k16.row.col.f32.f16.f16.f32 "
        "{%0,%1,%2,%3}, {%4,%5,%6,%7}, {%8,%9}, {%0,%1,%2,%3};"
        : "+f"(c[0]), "+f"(c[1]), "+f"(c[2]), "+f"(c[3])
        : "r"(a[0]), "r"(a[1]), "r"(a[2]), "r"(a[3]), "r"(b0), "r"(b1));
}
__device__ __forceinline__ void split_h(float f, __half& h, __half& l) {
    h = __float2half_rn(f);
    l = __float2half_rn(f - __half2float(h));
}
__device__ __forceinline__ uint32_t smem_u32(const void* p) {
    uint32_t a;
    asm("{ .reg .u64 t; cvta.to.shared.u64 t, %1; cvt.u32.u64 %0, t; }"
        : "=r"(a) : "l"(p));
    return a;
}
__device__ __forceinline__ void cp16(uint32_t s, const void* g) {
    asm volatile("cp.async.cg.shared.global [%0], [%1], 16;" :: "r"(s), "l"(g));
}
#define CP_COMMIT() asm volatile("cp.async.commit_group;" ::: "memory")
#define CP_WAIT(N)  asm volatile("cp.async.wait_group %0;" :: "n"(N) : "memory")

// ---------------------------------------------------------------------------
// prep_w: transpose W[k][c] -> WT[c][k], split fp16 hi/lo. grid(16,16,3).
// ---------------------------------------------------------------------------
__global__ void prep_w_kernel(const float* __restrict__ Wq,
                              const float* __restrict__ Wk,
                              const float* __restrict__ Wv)
{
    __shared__ float s[32][33];
    const float* W = (blockIdx.z == 0) ? Wq : (blockIdx.z == 1) ? Wk : Wv;
    __half* dh = g_WThi + (size_t)blockIdx.z * Dx * Dx;
    __half* dl = g_WTlo + (size_t)blockIdx.z * Dx * Dx;
    const int kt = blockIdx.y * 32, ct = blockIdx.x * 32;
    const int tid = threadIdx.x;
    {
        int r = tid >> 3, c4 = (tid & 7) * 4;
        float4 v = *reinterpret_cast<const float4*>(&W[(size_t)(kt + r) * Dx + ct + c4]);
        s[r][c4] = v.x; s[r][c4 + 1] = v.y; s[r][c4 + 2] = v.z; s[r][c4 + 3] = v.w;
    }
    __syncthreads();
    {
        int cw = tid >> 3, k4 = (tid & 7) * 4;
        size_t o = (size_t)(ct + cw) * Dx + kt + k4;
#pragma unroll
        for (int j = 0; j < 4; j += 2) {
            __half h0, l0, h1, l1;
            split_h(s[k4 + j][cw], h0, l0);
            split_h(s[k4 + j + 1][cw], h1, l1);
            *reinterpret_cast<__half2*>(&dh[o + j]) = __halves2half2(h0, h1);
            *reinterpret_cast<__half2*>(&dl[o + j]) = __halves2half2(l0, l1);
        }
    }
}

// ---------------------------------------------------------------------------
// prep_x: split x to fp16 hi/lo.
// ---------------------------------------------------------------------------
__global__ void prep_x_kernel(const float* __restrict__ X)
{
    size_t i4 = (size_t)blockIdx.x * 256 + threadIdx.x;
    float4 v = *reinterpret_cast<const float4*>(X + i4 * 4);
    __half h0, l0, h1, l1, h2, l2, h3, l3;
    split_h(v.x, h0, l0); split_h(v.y, h1, l1);
    split_h(v.z, h2, l2); split_h(v.w, h3, l3);
    size_t o = i4 * 4;
    *reinterpret_cast<__half2*>(&g_Xhi[o])     = __halves2half2(h0, h1);
    *reinterpret_cast<__half2*>(&g_Xhi[o + 2]) = __halves2half2(h2, h3);
    *reinterpret_cast<__half2*>(&g_Xlo[o])     = __halves2half2(l0, l1);
    *reinterpret_cast<__half2*>(&g_Xlo[o + 2]) = __halves2half2(l2, l3);
}

// ---------------------------------------------------------------------------
// proj_mma: Y = X @ W + b, f16 hi/lo split, cp.async double-buffered, BK=32.
// grid (4, 64, 3): z selects {Q, K, V}. Stage: Xh|Xl|Wh|Wl each 128xPSH halves.
// ---------------------------------------------------------------------------
#define PROJ_STAGE (4 * 128 * PSH)                 // halves per stage
#define PROJ_SMEM  (2 * PROJ_STAGE * 2)            // bytes (81920)

__global__ __launch_bounds__(256)
void proj_mma_kernel(const float* __restrict__ bq, const float* __restrict__ bk,
                     const float* __restrict__ bv)
{
    extern __shared__ __half smh[];
    const int tid = threadIdx.x;
    const int w = tid >> 5, lane = tid & 31;
    const int gr = lane >> 2, tc = lane & 3;
    const int wm = w >> 2, wn = w & 3;
    const int mbase = blockIdx.y * 128;
    const int nbase = blockIdx.x * 128;
    const int z = blockIdx.z;

    const __half* WTh = g_WThi + (size_t)z * Dx * Dx;
    const __half* WTl = g_WTlo + (size_t)z * Dx * Dx;
    const float* bias = (z == 0) ? bq : (z == 1) ? bk : bv;
    float* out = (z == 0) ? g_Q : (z == 1) ? g_K : g_V;
    __half* outHi = (z == 0) ? g_Qhi : (z == 1) ? g_Khi : (__half*)0;
    __half* outLo = (z == 0) ? g_Qlo : (z == 1) ? g_Klo : (__half*)0;

    const uint32_t sb0 = smem_u32(smh);

    // prefetch one stage: 4 buffers x 128 rows x 32 halves
    auto prefetch = [&](int kt_i, int stage) {
        const int kt = kt_i * 32;
        const uint32_t sb = sb0 + (uint32_t)(stage * PROJ_STAGE * 2);
#pragma unroll
        for (int i = 0; i < 8; i++) {
            int idx = tid + i * 256;
            int buf = idx >> 9;              // constant per i
            int within = idx & 511;
            int r = within >> 2;
            int u = (within & 3) * 8;
            uint32_t sa = sb + (uint32_t)((buf * 128 * PSH + r * PSH + u) * 2);
            const __half* gp;
            if (buf == 0)      gp = g_Xhi + (size_t)(mbase + r) * Dx + kt + u;
            else if (buf == 1) gp = g_Xlo + (size_t)(mbase + r) * Dx + kt + u;
            else if (buf == 2) gp = WTh + (size_t)(nbase + r) * Dx + kt + u;
            else               gp = WTl + (size_t)(nbase + r) * Dx + kt + u;
            cp16(sa, gp);
        }
        CP_COMMIT();
    };

    float C[16][4];
#pragma unroll
    for (int p = 0; p < 16; p++)
#pragma unroll
        for (int j = 0; j < 4; j++) C[p][j] = 0.f;

    prefetch(0, 0);

    for (int it = 0; it < 16; it++) {
        const int stage = it & 1;
        if (it < 15) { prefetch(it + 1, stage ^ 1); CP_WAIT(1); }
        else         { CP_WAIT(0); }
        __syncthreads();

        const __half* Xh = smh + stage * PROJ_STAGE;
        const __half* Xl = Xh + 128 * PSH;
        const __half* Wh = Xl + 128 * PSH;
        const __half* Wl = Wh + 128 * PSH;

#pragma unroll
        for (int k16 = 0; k16 < 2; k16++) {
            const int kw = k16 * 8;
            uint32_t ah[4][4], al[4][4];
#pragma unroll
            for (int mi = 0; mi < 4; mi++) {
                int row = (wm * 4 + mi) * 16 + gr;
                const uint32_t* ph = reinterpret_cast<const uint32_t*>(Xh) + row * PSW + kw;
                const uint32_t* pl = reinterpret_cast<const uint32_t*>(Xl) + row * PSW + kw;
                ah[mi][0] = ph[tc];           ah[mi][1] = ph[8 * PSW + tc];
                ah[mi][2] = ph[tc + 4];       ah[mi][3] = ph[8 * PSW + tc + 4];
                al[mi][0] = pl[tc];           al[mi][1] = pl[8 * PSW + tc];
                al[mi][2] = pl[tc + 4];       al[mi][3] = pl[8 * PSW + tc + 4];
            }
#pragma unroll
            for (int ni = 0; ni < 4; ni++) {
                int key = (wn * 4 + ni) * 8 + gr;
                const uint32_t* qh = reinterpret_cast<const uint32_t*>(Wh) + key * PSW + kw;
                const uint32_t* ql = reinterpret_cast<const uint32_t*>(Wl) + key * PSW + kw;
                uint32_t bh0 = qh[tc], bh1 = qh[tc + 4];
                uint32_t bl0 = ql[tc], bl1 = ql[tc + 4];
#pragma unroll
                for (int mi = 0; mi < 4; mi++) {
                    mma_f16(C[mi * 4 + ni], ah[mi], bh0, bh1);
                    mma_f16(C[mi * 4 + ni], ah[mi], bl0, bl1);
                    mma_f16(C[mi * 4 + ni], al[mi], bh0, bh1);
                }
            }
        }
        __syncthreads();
    }

    // epilogue: [bh][l][d] layout, fp32 (+ fp16 hi/lo for Q, K)
#pragma unroll
    for (int mi = 0; mi < 4; mi++) {
#pragma unroll
        for (int ni = 0; ni < 4; ni++) {
            const float* c = C[mi * 4 + ni];
            int col = nbase + (wn * 4 + ni) * 8 + 2 * tc;
            int h = col >> 6, d = col & 63;
            float b0 = bias[col], b1 = bias[col + 1];
#pragma unroll
            for (int half_ = 0; half_ < 2; half_++) {
                int r = mbase + (wm * 4 + mi) * 16 + gr + half_ * 8;
                int bb = r >> 11, l = r & 2047;
                size_t o = (((size_t)(bb * Hx + h)) * Lx + l) * DHx + d;
                float v0 = c[half_ * 2] + b0;
                float v1 = c[half_ * 2 + 1] + b1;
                *reinterpret_cast<float2*>(&out[o]) = make_float2(v0, v1);
                if (outHi) {
                    __half h0, l0, h1, l1;
                    split_h(v0, h0, l0);
                    split_h(v1, h1, l1);
                    *reinterpret_cast<__half2*>(&outHi[o]) = __halves2half2(h0, h1);
                    *reinterpret_cast<__half2*>(&outLo[o]) = __halves2half2(l0, l1);
                }
            }
        }
    }
}

// ---------------------------------------------------------------------------
// score_mma: rowmax(Q[128,64] @ K^T) f16 hi/lo; K cp.async double-buffered.
// smem: Qh|Ql resident, K stages x2 (Kh|Kl), red.
// ---------------------------------------------------------------------------
#define KSTAGE (2 * 128 * SH)   // halves per K stage
#define SCORE_SMEM ((2 * 128 * SH + 2 * KSTAGE) * 2 + 4 * 128 * 4)

__global__ __launch_bounds__(256)
void score_mma_kernel()
{
    extern __shared__ __half smh[];
    __half* Qh = smh;
    __half* Ql = Qh + 128 * SH;
    __half* Kst = Ql + 128 * SH;             // 2 stages follow
    float* red = reinterpret_cast<float*>(Kst + 2 * KSTAGE);

    const int tid = threadIdx.x;
    const int w = tid >> 5, lane = tid & 31;
    const int gr = lane >> 2, tc = lane & 3;
    const int wm = w >> 2, wn = w & 3;
    const int bh = blockIdx.y;
    const int qbase = blockIdx.x * 128;

    const uint32_t kst_u32 = smem_u32(Kst);

    auto prefetch_k = [&](int t, int stage) {
        const uint32_t sb = kst_u32 + (uint32_t)(stage * KSTAGE * 2);
#pragma unroll
        for (int i = 0; i < 8; i++) {
            int idx = tid + i * 256;
            int buf = idx >> 10;             // 0=hi, 1=lo (constant per i pairs)
            int within = idx & 1023;
            int r = within >> 3;
            int u = (within & 7) * 8;
            uint32_t sa = sb + (uint32_t)((buf * 128 * SH + r * SH + u) * 2);
            const __half* gp = (buf == 0 ? g_Khi : g_Klo)
                               + ((size_t)bh * Lx + t * 128 + r) * DHx + u;
            cp16(sa, gp);
        }
        CP_COMMIT();
    };

    // Q fill once (regular loads)
#pragma unroll
    for (int i = 0; i < 4; i++) {
        int idx = tid + i * 256;
        int r = idx >> 3;
        int u = (idx & 7) * 8;
        size_t qs = ((size_t)bh * Lx + qbase + r) * DHx + u;
        *reinterpret_cast<uint4*>(Qh + r * SH + u) =
            *reinterpret_cast<const uint4*>(g_Qhi + qs);
        *reinterpret_cast<uint4*>(Ql + r * SH + u) =
            *reinterpret_cast<const uint4*>(g_Qlo + qs);
    }

    prefetch_k(0, 0);

    float rm0[4], rm1[4];
#pragma unroll
    for (int mi = 0; mi < 4; mi++) { rm0[mi] = -1e30f; rm1[mi] = -1e30f; }

    for (int t = 0; t < 16; t++) {
        const int stage = t & 1;
        if (t < 15) { prefetch_k(t + 1, stage ^ 1); CP_WAIT(1); }
        else        { CP_WAIT(0); }
        __syncthreads();

        const __half* Kh = Kst + stage * KSTAGE;
        const __half* Kl = Kh + 128 * SH;

        float C[16][4];
#pragma unroll
        for (int p = 0; p < 16; p++)
#pragma unroll
            for (int j = 0; j < 4; j++) C[p][j] = 0.f;

#pragma unroll
        for (int k16 = 0; k16 < 4; k16++) {
            const int kw = k16 * 8;
            uint32_t ah[4][4], al[4][4];
#pragma unroll
            for (int mi = 0; mi < 4; mi++) {
                int row = (wm * 4 + mi) * 16 + gr;
                const uint32_t* ph = reinterpret_cast<const uint32_t*>(Qh) + row * SW + kw;
                const uint32_t* pl = reinterpret_cast<const uint32_t*>(Ql) + row * SW + kw;
                ah[mi][0] = ph[tc];           ah[mi][1] = ph[8 * SW + tc];
                ah[mi][2] = ph[tc + 4];       ah[mi][3] = ph[8 * SW + tc + 4];
                al[mi][0] = pl[tc];           al[mi][1] = pl[8 * SW + tc];
                al[mi][2] = pl[tc + 4];       al[mi][3] = pl[8 * SW + tc + 4];
            }
#pragma unroll
            for (int ni = 0; ni < 4; ni++) {
                int key = (wn * 4 + ni) * 8 + gr;
                const uint32_t* qh = reinterpret_cast<const uint32_t*>(Kh) + key * SW + kw;
                const uint32_t* ql = reinterpret_cast<const uint32_t*>(Kl) + key * SW + kw;
                uint32_t bh0 = qh[tc], bh1 = qh[tc + 4];
                uint32_t bl0 = ql[tc], bl1 = ql[tc + 4];
#pragma unroll
                for (int mi = 0; mi < 4; mi++) {
                    mma_f16(C[mi * 4 + ni], ah[mi], bh0, bh1);
                    mma_f16(C[mi * 4 + ni], ah[mi], bl0, bl1);
                    mma_f16(C[mi * 4 + ni], al[mi], bh0, bh1);
                }
            }
        }

#pragma unroll
        for (int mi = 0; mi < 4; mi++)
#pragma unroll
            for (int ni = 0; ni < 4; ni++) {
                const float* c = C[mi * 4 + ni];
                rm0[mi] = fmaxf(rm0[mi], fmaxf(c[0], c[1]));
                rm1[mi] = fmaxf(rm1[mi], fmaxf(c[2], c[3]));
            }
        __syncthreads();
    }

#pragma unroll
    for (int mi = 0; mi < 4; mi++) {
        rm0[mi] = fmaxf(rm0[mi], __shfl_xor_sync(0xffffffffu, rm0[mi], 1));
        rm0[mi] = fmaxf(rm0[mi], __shfl_xor_sync(0xffffffffu, rm0[mi], 2));
        rm1[mi] = fmaxf(rm1[mi], __shfl_xor_sync(0xffffffffu, rm1[mi], 1));
        rm1[mi] = fmaxf(rm1[mi], __shfl_xor_sync(0xffffffffu, rm1[mi], 2));
    }
    if (tc == 0) {
#pragma unroll
        for (int mi = 0; mi < 4; mi++) {
            int row = (wm * 4 + mi) * 16 + gr;
            red[wn * 128 + row] = rm0[mi];
            red[wn * 128 + row + 8] = rm1[mi];
        }
    }
    __syncthreads();
    if (tid < 128) {
        float m = fmaxf(fmaxf(red[tid], red[128 + tid]),
                        fmaxf(red[256 + tid], red[384 + tid]));
        g_rowmax[(size_t)bh * Lx + qbase + tid] = m;
    }
}

// ---------------------------------------------------------------------------
// K / V column sums.
// ---------------------------------------------------------------------------
__global__ void zero_sums_kernel()
{
    int i = blockIdx.x * blockDim.x + threadIdx.x;
    if (i < BHx * DHx) { g_Ksum[i] = 0.f; g_Vsum[i] = 0.f; }
}

__global__ void partial_sums_kernel()
{
    const int bh = blockIdx.x;
    const int kb = blockIdx.y * 128;
    const int tid = threadIdx.x;
    const int d = tid & 63, s = tid >> 6;
    float ks = 0.f, vs = 0.f;
    for (int k = kb + s; k < kb + 128; k += 4) {
        ks += g_K[((size_t)bh * Lx + k) * DHx + d];
        vs += g_V[((size_t)bh * Lx + k) * DHx + d];
    }
    __shared__ float red[2][256];
    red[0][tid] = ks;
    red[1][tid] = vs;
    __syncthreads();
    if (tid < 64) {
        float a = red[0][d] + red[0][d + 64] + red[0][d + 128] + red[0][d + 192];
        float b = red[1][d] + red[1][d + 64] + red[1][d + 128] + red[1][d + 192];
        atomicAdd(&g_Ksum[bh * DHx + d], a);
        atomicAdd(&g_Vsum[bh * DHx + d], b);
    }
}

// ---------------------------------------------------------------------------
// M = SCALE * (rowmax - Q.Ksum / L)
// ---------------------------------------------------------------------------
__global__ void mstat_kernel()
{
    int gidx = blockIdx.x * 256 + threadIdx.x;
    int bh = gidx >> 11;
    const float* qp = g_Q + (size_t)gidx * DHx;
    const float* ks = g_Ksum + bh * DHx;
    float dot = 0.f;
#pragma unroll
    for (int d = 0; d < DHx; d += 4) {
        float4 a = *reinterpret_cast<const float4*>(qp + d);
        float4 b = *reinterpret_cast<const float4*>(ks + d);
        dot += a.x * b.x + a.y * b.y + a.z * b.z + a.w * b.w;
    }
    g_M[gidx] = SCALEF * (g_rowmax[gidx] - dot * (1.0f / Lx));
}

// ---------------------------------------------------------------------------
// Top-38 selection per bh.
// ---------------------------------------------------------------------------
__global__ void topk_kernel()
{
    int bh = blockIdx.x;
    int tid = threadIdx.x;
    __shared__ float vals[Lx];
    __shared__ float rv[256];
    __shared__ int ri[256];
    for (int i = tid; i < Lx; i += 256) vals[i] = g_M[(size_t)bh * Lx + i];
    __syncthreads();
    for (int it = 0; it < KTOP; it++) {
        float best = -1e30f;
        int bidx = 0;
        for (int i = tid; i < Lx; i += 256) {
            float v = vals[i];
            if (v > best) { best = v; bidx = i; }
        }
        rv[tid] = best;
        ri[tid] = bidx;
        __syncthreads();
        for (int s = 128; s > 0; s >>= 1) {
            if (tid < s) {
                if (rv[tid + s] > rv[tid] ||
                    (rv[tid + s] == rv[tid] && ri[tid + s] < ri[tid])) {
                    rv[tid] = rv[tid + s];
                    ri[tid] = ri[tid + s];
                }
            }
            __syncthreads();
        }
        if (tid == 0) {
            g_top[bh * KTOP + it] = ri[0];
            vals[ri[0]] = -1e30f;
        }
        __syncthreads();
    }
}

// ---------------------------------------------------------------------------
// Sparse attention, 2 queries per block (exact fp32).
// ---------------------------------------------------------------------------
__global__ __launch_bounds__(256)
void sparse_attn_kernel()
{
    const int bh = blockIdx.y;
    const int i0 = blockIdx.x;
    const int i1 = blockIdx.x + KHALF;
    const int tid = threadIdx.x;
    const int q0 = g_top[bh * KTOP + i0];
    const int q1 = g_top[bh * KTOP + i1];

    __shared__ float sc0[Lx];
    __shared__ float sc1[Lx];
    __shared__ float qrow[2][DHx];
    __shared__ float red[256];

    if (tid < 64) {
        qrow[0][tid] = g_Q[((size_t)bh * Lx + q0) * DHx + tid];
        qrow[1][tid] = g_Q[((size_t)bh * Lx + q1) * DHx + tid];
    }
    __syncthreads();

    const int warp = tid >> 5, lane = tid & 31;
    const float qa0 = qrow[0][lane], qa1 = qrow[0][lane + 32];
    const float qb0 = qrow[1][lane], qb1 = qrow[1][lane + 32];
    for (int k = warp; k < Lx; k += 8) {
        const float* kr = g_K + ((size_t)bh * Lx + k) * DHx;
        float k0 = kr[lane], k1 = kr[lane + 32];
        float pa = k0 * qa0 + k1 * qa1;
        float pb = k0 * qb0 + k1 * qb1;
#pragma unroll
        for (int o = 16; o > 0; o >>= 1) {
            pa += __shfl_xor_sync(0xffffffffu, pa, o);
            pb += __shfl_xor_sync(0xffffffffu, pb, o);
        }
        if (lane == 0) { sc0[k] = pa * SCALEF; sc1[k] = pb * SCALEF; }
    }
    __syncthreads();

    float inv0, inv1;
    for (int qq = 0; qq < 2; qq++) {
        float* sc = qq ? sc1 : sc0;
        float mx = -1e30f;
        for (int k = tid; k < Lx; k += 256) mx = fmaxf(mx, sc[k]);
        red[tid] = mx;
        __syncthreads();
        for (int s = 128; s > 0; s >>= 1) {
            if (tid < s) red[tid] = fmaxf(red[tid], red[tid + s]);
            __syncthreads();
        }
        mx = red[0];
        __syncthreads();
        float sum = 0.f;
        for (int k = tid; k < Lx; k += 256) {
            float e = __expf(sc[k] - mx);
            sc[k] = e;
            sum += e;
        }
        red[tid] = sum;
        __syncthreads();
        for (int s = 128; s > 0; s >>= 1) {
            if (tid < s) red[tid] += red[tid + s];
            __syncthreads();
        }
        if (qq == 0) inv0 = 1.0f / red[0]; else inv1 = 1.0f / red[0];
        __syncthreads();
    }

    const int d = tid & 63, s4 = tid >> 6;
    float acc0 = 0.f, acc1 = 0.f;
    for (int k = s4; k < Lx; k += 4) {
        float v = g_V[((size_t)bh * Lx + k) * DHx + d];
        acc0 += sc0[k] * v;
        acc1 += sc1[k] * v;
    }
    __shared__ float red2[2][256];
    red2[0][tid] = acc0;
    red2[1][tid] = acc1;
    __syncthreads();
    if (tid < 64) {
        float vm = g_Vsum[bh * DHx + d] * (1.0f / Lx);
        float c0 = (red2[0][d] + red2[0][d + 64] + red2[0][d + 128] + red2[0][d + 192]) * inv0;
        float c1 = (red2[1][d] + red2[1][d + 64] + red2[1][d + 128] + red2[1][d + 192]) * inv1;
        g_delta[((size_t)bh * KTOP + i0) * DHx + d] = c0 - vm;
        g_delta[((size_t)bh * KTOP + i1) * DHx + d] = c1 - vm;
    }
}

// ---------------------------------------------------------------------------
__global__ void base_kernel(const float* __restrict__ Wo, const float* __restrict__ bo)
{
    int b = blockIdx.x, j = threadIdx.x;
    float acc = bo[j];
    for (int c = 0; c < Dx; c++) {
        int h = c >> 6, d = c & 63;
        acc += g_Vsum[(b * Hx + h) * DHx + d] * (1.0f / Lx) * Wo[(size_t)c * Dx + j];
    }
    g_base[b * Dx + j] = acc;
}

__global__ void fill_kernel(float* __restrict__ out)
{
    size_t idx = (size_t)blockIdx.x * blockDim.x + threadIdx.x;
    if (idx < (size_t)Bx * Lx * Dx) {
        int b = (int)(idx / ((size_t)Lx * Dx));
        int j = (int)(idx % Dx);
        out[idx] = g_base[b * Dx + j];
    }
}

__global__ void scatter_kernel(const float* __restrict__ Wo, float* __restrict__ out)
{
    const int bh = blockIdx.y;
    const int i = blockIdx.x;
    const int j = threadIdx.x;  // 512
    const int b = bh >> 3, h = bh & 7;
    const int l = g_top[bh * KTOP + i];
    __shared__ float dl[DHx];
    if (j < 64) dl[j] = g_delta[((size_t)bh * KTOP + i) * DHx + j];
    __syncthreads();
    float acc = 0.f;
#pragma unroll 16
    for (int d = 0; d < 64; d++) acc += dl[d] * Wo[(size_t)(h * 64 + d) * Dx + j];
    atomicAdd(&out[((size_t)b * Lx + l) * Dx + j], acc);
}

// ---------------------------------------------------------------------------
extern "C" void kernel_launch(void* const* d_in, const int* in_sizes, int n_in,
                              void* d_out, int out_size)
{
    const float* x  = (const float*)d_in[0];
    const float* Wq = (const float*)d_in[1];
    const float* bq = (const float*)d_in[2];
    const float* Wk = (const float*)d_in[3];
    const float* bk = (const float*)d_in[4];
    const float* Wv = (const float*)d_in[5];
    const float* bv = (const float*)d_in[6];
    const float* Wo = (const float*)d_in[7];
    const float* bo = (const float*)d_in[8];
    float* out = (float*)d_out;

    (void)in_sizes; (void)n_in; (void)out_size;

    cudaFuncSetAttribute(proj_mma_kernel,
                         cudaFuncAttributeMaxDynamicSharedMemorySize, PROJ_SMEM);
    cudaFuncSetAttribute(score_mma_kernel,
                         cudaFuncAttributeMaxDynamicSharedMemorySize, SCORE_SMEM);

    prep_w_kernel<<<dim3(16, 16, 3), 256>>>(Wq, Wk, Wv);          // 0
    prep_x_kernel<<<(Bx * Lx * Dx / 4) / 256, 256>>>(x);          // 1

    dim3 pg(Dx / 128, (Bx * Lx) / 128, 3);  // (4, 64, 3)
    proj_mma_kernel<<<pg, 256, PROJ_SMEM>>>(bq, bk, bv);          // 2

    zero_sums_kernel<<<(BHx * DHx + 255) / 256, 256>>>();         // 3
    partial_sums_kernel<<<dim3(BHx, 16), 256>>>();                // 4

    // launch index 5 -> ncu capture target (-s 5 -c 1)
    score_mma_kernel<<<dim3(Lx / 128, BHx), 256, SCORE_SMEM>>>(); // 5

    mstat_kernel<<<BHx * Lx / 256, 256>>>();

    topk_kernel<<<BHx, 256>>>();

    sparse_attn_kernel<<<dim3(KHALF, BHx), 256>>>();

    base_kernel<<<Bx, Dx>>>(Wo, bo);
    fill_kernel<<<(Bx * Lx * Dx + 255) / 256, 256>>>(out);
    scatter_kernel<<<dim3(KTOP, BHx), Dx>>>(Wo, out);
}